// round 5
// baseline (speedup 1.0000x reference)
#include <cuda_runtime.h>
#include <cuda_bf16.h>
#include <cstdint>

// Problem constants (verified against reference setup_inputs)
#define NN 100000
#define NE 1600000
#define D1 1024
#define D2 512
#define D3 128

// ---------------- scratch (static __device__; referenced ONLY from device code) ----------------
__device__ float g_xw1[(size_t)NN * D2];    // node_attr @ W1
__device__ float g_h1 [(size_t)NN * D2];    // relu(gcn1)
__device__ float g_xw2[(size_t)NN * D3];    // h1 @ W2
__device__ float g_deg1[NN];
__device__ float g_dinv1[NN];
__device__ float g_dinv2[NN];
__device__ float g_ssrc[NN];
__device__ float g_sdst[NN];
__device__ int   g_counts[NN];
__device__ int   g_rowptr[NN + 1];
__device__ int   g_cursor[NN];
__device__ int   g_csr_src[NE];
__device__ float g_csr_w[NE];    // edge_weight * dinv1[src]
__device__ float g_csr_e2[NE];   // e2 (later scaled by dinv2[src] in-place)
__device__ int   g_is64;         // 1 if edge_index is int64 on device, else 0 (int32)

// ---------------- edge_index dtype detection ----------------
// If int64 with values < 2^31 (node ids < 100000), every odd 32-bit word is 0.
// If int32, the odd words are real indices (P[all 32 zero] ~ (1e-5)^32 ~ 0).
__global__ void detect_kernel(const int* __restrict__ ei32) {
    unsigned lane = threadIdx.x;
    int v = ei32[2 * lane + 1];
    unsigned b = __ballot_sync(0xffffffffu, v == 0);
    if (lane == 0) g_is64 = (b == 0xffffffffu) ? 1 : 0;
}

__device__ __forceinline__ int load_idx(const int* ei32, size_t pos, int n) {
    int v;
    if (g_is64) v = (int)((const long long*)ei32)[pos];
    else        v = ei32[pos];
    // clamp defensively: wrong dtype shows up as rel_err, never as a wild address
    return min(max(v, 0), n - 1);
}

// ---------------- CSR construction ----------------
__global__ void init_nodes_kernel(int n) {
    int i = blockIdx.x * blockDim.x + threadIdx.x;
    if (i < n) { g_deg1[i] = 1.0f; g_counts[i] = 0; }   // self-loop weight 1
}

__global__ void edge_count_kernel(const int* __restrict__ ei,
                                  const float* __restrict__ ew, int E, int n) {
    int e = blockIdx.x * blockDim.x + threadIdx.x;
    if (e >= E) return;
    int col = load_idx(ei, (size_t)E + e, n);
    atomicAdd(&g_counts[col], 1);
    atomicAdd(&g_deg1[col], ew[e]);
}

__global__ void dinv1_kernel(int n) {
    int i = blockIdx.x * blockDim.x + threadIdx.x;
    if (i < n) {
        float d = g_deg1[i];
        g_dinv1[i] = (d > 0.0f) ? rsqrtf(d) : 0.0f;
    }
}

// Single-block chunked exclusive scan over counts -> rowptr (+cursor copy)
__global__ void scan_kernel(int n) {
    __shared__ int wsum[32];
    __shared__ int s_carry;
    const int tid = threadIdx.x, lane = tid & 31, warp = tid >> 5;
    if (tid == 0) s_carry = 0;
    __syncthreads();
    for (int base = 0; base < n; base += 1024) {
        int i = base + tid;
        int v = (i < n) ? g_counts[i] : 0;
        int incl = v;
        #pragma unroll
        for (int o = 1; o < 32; o <<= 1) {
            int t = __shfl_up_sync(0xffffffffu, incl, o);
            if (lane >= o) incl += t;
        }
        if (lane == 31) wsum[warp] = incl;
        __syncthreads();
        if (warp == 0) {
            int s = wsum[lane];
            #pragma unroll
            for (int o = 1; o < 32; o <<= 1) {
                int t = __shfl_up_sync(0xffffffffu, s, o);
                if (lane >= o) s += t;
            }
            wsum[lane] = s;
        }
        __syncthreads();
        int excl = s_carry + (warp ? wsum[warp - 1] : 0) + incl - v;
        if (i < n) { g_rowptr[i] = excl; g_cursor[i] = excl; }
        int total = wsum[31];
        __syncthreads();
        if (tid == 0) s_carry += total;
        __syncthreads();
    }
    if (tid == 0) g_rowptr[n] = s_carry;
}

__global__ void fill_kernel(const int* __restrict__ ei,
                            const float* __restrict__ ew, int E, int n) {
    int e = blockIdx.x * blockDim.x + threadIdx.x;
    if (e >= E) return;
    int row = load_idx(ei, (size_t)e, n);
    int col = load_idx(ei, (size_t)E + e, n);
    int pos = atomicAdd(&g_cursor[col], 1);
    g_csr_src[pos] = row;
    g_csr_w[pos]   = ew[e] * g_dinv1[row];
}

// ---------------- fp32 SGEMM body: C[M,N] = A[M,K] @ B[K,N]; N%128==0, K%8==0 ----------------
template <int BM, int BN, int BK, int TM, int TN>
__device__ __forceinline__ void sgemm_body(const float* __restrict__ A,
                                           const float* __restrict__ B,
                                           float* __restrict__ C,
                                           int M, int N, int K) {
    __shared__ float As[BK][BM];
    __shared__ float Bs[BK][BN];
    const int tid = threadIdx.x;
    const int rowTile = blockIdx.y * BM;
    const int colTile = blockIdx.x * BN;
    const int threadRow = tid / (BN / TN);
    const int threadCol = tid % (BN / TN);
    const int aRow = tid / (BK / 4);
    const int aCol = (tid % (BK / 4)) * 4;
    const int bRow = tid / (BN / 4);
    const int bCol = (tid % (BN / 4)) * 4;

    float acc[TM][TN];
    #pragma unroll
    for (int i = 0; i < TM; i++)
        #pragma unroll
        for (int j = 0; j < TN; j++) acc[i][j] = 0.0f;
    float regM[TM], regN[TN];

    for (int k0 = 0; k0 < K; k0 += BK) {
        float4 av = make_float4(0.f, 0.f, 0.f, 0.f);
        int ar = rowTile + aRow;
        if (ar < M) av = *(const float4*)&A[(size_t)ar * K + k0 + aCol];
        As[aCol + 0][aRow] = av.x;
        As[aCol + 1][aRow] = av.y;
        As[aCol + 2][aRow] = av.z;
        As[aCol + 3][aRow] = av.w;
        float4 bv = *(const float4*)&B[(size_t)(k0 + bRow) * N + colTile + bCol];
        *(float4*)&Bs[bRow][bCol] = bv;
        __syncthreads();
        #pragma unroll
        for (int k = 0; k < BK; k++) {
            #pragma unroll
            for (int i = 0; i < TM; i++) regM[i] = As[k][threadRow * TM + i];
            #pragma unroll
            for (int j = 0; j < TN; j++) regN[j] = Bs[k][threadCol * TN + j];
            #pragma unroll
            for (int i = 0; i < TM; i++)
                #pragma unroll
                for (int j = 0; j < TN; j++)
                    acc[i][j] = fmaf(regM[i], regN[j], acc[i][j]);
        }
        __syncthreads();
    }
    #pragma unroll
    for (int i = 0; i < TM; i++) {
        int r = rowTile + threadRow * TM + i;
        if (r < M) {
            #pragma unroll
            for (int j = 0; j < TN; j += 4) {
                float4 v = make_float4(acc[i][j], acc[i][j + 1], acc[i][j + 2], acc[i][j + 3]);
                *(float4*)&C[(size_t)r * N + colTile + threadCol * TN + j] = v;
            }
        }
    }
}

// GEMM1: g_xw1 = node_attr @ W1  (symbols bound in device code)
__global__ void __launch_bounds__(256, 2)
sgemm1_kernel(const float* __restrict__ A, const float* __restrict__ B, int M) {
    sgemm_body<128, 128, 8, 8, 8>(A, B, &g_xw1[0], M, D2, D1);
}

// GEMM2: g_xw2 = g_h1 @ W2
__global__ void __launch_bounds__(256, 2)
sgemm2_kernel(const float* __restrict__ B, int M) {
    sgemm_body<128, 128, 8, 8, 8>(&g_h1[0], B, &g_xw2[0], M, D3, D2);
}

// ---------------- layer-1 aggregation (block of 128 threads per destination node) ----------------
__global__ void aggregate1_kernel(const float* __restrict__ b1, int n) {
    const int j = blockIdx.x;
    const int tid = threadIdx.x;  // 128
    __shared__ int   s_src[128];
    __shared__ float s_w[128];
    const int start = g_rowptr[j];
    const int end   = g_rowptr[j + 1];
    float4 acc = make_float4(0.f, 0.f, 0.f, 0.f);
    for (int base = start; base < end; base += 128) {
        int ne = min(128, end - base);
        __syncthreads();
        if (tid < ne) { s_src[tid] = g_csr_src[base + tid]; s_w[tid] = g_csr_w[base + tid]; }
        __syncthreads();
        for (int i = 0; i < ne; i++) {
            const float4 v = *(const float4*)&g_xw1[(size_t)s_src[i] * D2 + tid * 4];
            const float w = s_w[i];
            acc.x = fmaf(w, v.x, acc.x);
            acc.y = fmaf(w, v.y, acc.y);
            acc.z = fmaf(w, v.z, acc.z);
            acc.w = fmaf(w, v.w, acc.w);
        }
    }
    const float di  = g_dinv1[j];
    const float di2 = di * di;
    const float4 sv = *(const float4*)&g_xw1[(size_t)j * D2 + tid * 4];
    const float4 bb = *(const float4*)&b1[tid * 4];
    float4 o;
    o.x = fmaxf(fmaf(di, acc.x, fmaf(di2, sv.x, bb.x)), 0.f);
    o.y = fmaxf(fmaf(di, acc.y, fmaf(di2, sv.y, bb.y)), 0.f);
    o.z = fmaxf(fmaf(di, acc.z, fmaf(di2, sv.z, bb.z)), 0.f);
    o.w = fmaxf(fmaf(di, acc.w, fmaf(di2, sv.w, bb.w)), 0.f);
    *(float4*)&g_h1[(size_t)j * D2 + tid * 4] = o;
}

// ---------------- per-node similarity projections: s_src = h1@Wm[:512], s_dst = h1@Wm[512:] ----------------
__global__ void sim_kernel(const float* __restrict__ Wm, int n) {
    const int gw = (blockIdx.x * blockDim.x + threadIdx.x) >> 5;
    const int lane = threadIdx.x & 31;
    if (gw >= n) return;
    const float* hr = &g_h1[0] + (size_t)gw * D2;
    float a = 0.f, b = 0.f;
    #pragma unroll 4
    for (int k = lane; k < D2; k += 32) {
        float h = hr[k];
        a = fmaf(h, Wm[k], a);
        b = fmaf(h, Wm[D2 + k], b);
    }
    #pragma unroll
    for (int o = 16; o; o >>= 1) {
        a += __shfl_down_sync(0xffffffffu, a, o);
        b += __shfl_down_sync(0xffffffffu, b, o);
    }
    if (lane == 0) { g_ssrc[gw] = a; g_sdst[gw] = b; }
}

// ---------------- deg2 / e2 (warp per destination node) ----------------
__global__ void deg2_kernel(const float* __restrict__ bm, int n) {
    const int j = (blockIdx.x * blockDim.x + threadIdx.x) >> 5;
    const int lane = threadIdx.x & 31;
    if (j >= n) return;
    const float sd = g_sdst[j] + bm[0];
    const int start = g_rowptr[j], end = g_rowptr[j + 1];
    float sum = 0.f;
    for (int e = start + lane; e < end; e += 32) {
        float e2 = fmaxf(g_ssrc[g_csr_src[e]] + sd, 0.f);
        g_csr_e2[e] = e2;
        sum += e2;
    }
    #pragma unroll
    for (int o = 16; o; o >>= 1) sum += __shfl_down_sync(0xffffffffu, sum, o);
    if (lane == 0) g_dinv2[j] = rsqrtf(1.0f + sum);   // deg2 >= 1 always
}

__global__ void w2_kernel(int E) {
    int e = blockIdx.x * blockDim.x + threadIdx.x;
    if (e < E) g_csr_e2[e] *= g_dinv2[g_csr_src[e]];
}

// ---------------- layer-2 aggregation (warp per node, 128 dims) ----------------
__global__ void aggregate2_kernel(const float* __restrict__ b2,
                                  float* __restrict__ out, int n) {
    const int j = (blockIdx.x * blockDim.x + threadIdx.x) >> 5;
    const int lane = threadIdx.x & 31;
    if (j >= n) return;
    const int start = g_rowptr[j], end = g_rowptr[j + 1];
    float4 acc = make_float4(0.f, 0.f, 0.f, 0.f);
    for (int e = start; e < end; e++) {
        int s = g_csr_src[e];       // broadcast load within warp
        float w = g_csr_e2[e];      // e2 * dinv2[src]
        const float4 v = *(const float4*)&g_xw2[(size_t)s * D3 + lane * 4];
        acc.x = fmaf(w, v.x, acc.x);
        acc.y = fmaf(w, v.y, acc.y);
        acc.z = fmaf(w, v.z, acc.z);
        acc.w = fmaf(w, v.w, acc.w);
    }
    const float di = g_dinv2[j];
    const float di2 = di * di;
    const float4 sv = *(const float4*)&g_xw2[(size_t)j * D3 + lane * 4];
    const float4 bb = *(const float4*)&b2[lane * 4];
    float4 o;
    o.x = fmaf(di, acc.x, fmaf(di2, sv.x, bb.x));
    o.y = fmaf(di, acc.y, fmaf(di2, sv.y, bb.y));
    o.z = fmaf(di, acc.z, fmaf(di2, sv.z, bb.z));
    o.w = fmaf(di, acc.w, fmaf(di2, sv.w, bb.w));
    *(float4*)&out[(size_t)j * D3 + lane * 4] = o;
}

// ---------------- launch ----------------
extern "C" void kernel_launch(void* const* d_in, const int* in_sizes, int n_in,
                              void* d_out, int out_size) {
    const float* node_attr  = (const float*)d_in[0];
    const float* edge_attr  = (const float*)d_in[1];
    const int*   edge_index = (const int*)d_in[2];   // int32 per metadata contract (int64 auto-detected)
    // d_in[3] coords, d_in[4] frame: unused
    const float* W1 = (const float*)d_in[5];
    const float* b1 = (const float*)d_in[6];
    const float* W2 = (const float*)d_in[7];
    const float* b2 = (const float*)d_in[8];
    const float* Wm = (const float*)d_in[9];
    const float* bm = (const float*)d_in[10];
    float* out = (float*)d_out;

    const int n = in_sizes[0] / D1;   // 100000
    const int E = in_sizes[1];        // 1600000

    const int TB = 256;
    // dtype probe + CSR build + deg1
    detect_kernel<<<1, 32>>>(edge_index);
    init_nodes_kernel<<<(n + TB - 1) / TB, TB>>>(n);
    edge_count_kernel<<<(E + TB - 1) / TB, TB>>>(edge_index, edge_attr, E, n);
    dinv1_kernel<<<(n + TB - 1) / TB, TB>>>(n);
    scan_kernel<<<1, 1024>>>(n);
    fill_kernel<<<(E + TB - 1) / TB, TB>>>(edge_index, edge_attr, E, n);

    // GEMM1: xw1 = node_attr @ W1   [100000,1024]x[1024,512]
    {
        dim3 grid(D2 / 128, (n + 127) / 128);
        sgemm1_kernel<<<grid, 256>>>(node_attr, W1, n);
    }
    // layer-1 aggregate + relu -> h1
    aggregate1_kernel<<<n, 128>>>(b1, n);

    // per-node similarity projections
    sim_kernel<<<(n * 32 + TB - 1) / TB, TB>>>(Wm, n);
    // e2 per edge + deg2 -> dinv2
    deg2_kernel<<<(n * 32 + TB - 1) / TB, TB>>>(bm, n);
    w2_kernel<<<(E + TB - 1) / TB, TB>>>(E);

    // GEMM2: xw2 = h1 @ W2  [100000,512]x[512,128]
    {
        dim3 grid(D3 / 128, (n + 127) / 128);
        sgemm2_kernel<<<grid, 256>>>(W2, n);
    }
    // layer-2 aggregate -> out
    aggregate2_kernel<<<(n * 32 + TB - 1) / TB, TB>>>(b2, out, n);
}

// round 6
// speedup vs baseline: 1.5780x; 1.5780x over previous
#include <cuda_runtime.h>
#include <cuda_bf16.h>
#include <cstdint>

// Problem constants (verified against reference setup_inputs)
#define NN 100000
#define NE 1600000
#define D1 1024
#define D2 512
#define D3 128

// ---------------- scratch (static __device__; referenced ONLY from device code) ----------------
__device__ float g_xw1[(size_t)NN * D2];    // node_attr @ W1
__device__ float g_h1 [(size_t)NN * D2];    // relu(gcn1)
__device__ float g_xw2[(size_t)NN * D3];    // h1 @ W2
__device__ float g_deg1[NN];
__device__ float g_dinv1[NN];
__device__ float g_dinv2[NN];
__device__ float g_ssrc[NN];
__device__ float g_sdst[NN];
__device__ int   g_counts[NN];
__device__ int   g_rowptr[NN + 1];
__device__ int   g_cursor[NN];
__device__ int   g_csr_src[NE];
__device__ float g_csr_w[NE];    // edge_weight * dinv1[src]
__device__ float g_csr_e2[NE];   // e2 (later scaled by dinv2[src] in-place)
__device__ int   g_is64;         // 1 if edge_index is int64 on device, else 0 (int32)

// ---------------- edge_index dtype detection ----------------
__global__ void detect_kernel(const int* __restrict__ ei32) {
    unsigned lane = threadIdx.x;
    int v = ei32[2 * lane + 1];
    unsigned b = __ballot_sync(0xffffffffu, v == 0);
    if (lane == 0) g_is64 = (b == 0xffffffffu) ? 1 : 0;
}

__device__ __forceinline__ int load_idx(const int* ei32, size_t pos, int n) {
    int v;
    if (g_is64) v = (int)((const long long*)ei32)[pos];
    else        v = ei32[pos];
    return min(max(v, 0), n - 1);
}

// ---------------- CSR construction ----------------
__global__ void init_nodes_kernel(int n) {
    int i = blockIdx.x * blockDim.x + threadIdx.x;
    if (i < n) { g_deg1[i] = 1.0f; g_counts[i] = 0; }
}

__global__ void edge_count_kernel(const int* __restrict__ ei,
                                  const float* __restrict__ ew, int E, int n) {
    int e = blockIdx.x * blockDim.x + threadIdx.x;
    if (e >= E) return;
    int col = load_idx(ei, (size_t)E + e, n);
    atomicAdd(&g_counts[col], 1);
    atomicAdd(&g_deg1[col], ew[e]);
}

__global__ void dinv1_kernel(int n) {
    int i = blockIdx.x * blockDim.x + threadIdx.x;
    if (i < n) {
        float d = g_deg1[i];
        g_dinv1[i] = (d > 0.0f) ? rsqrtf(d) : 0.0f;
    }
}

__global__ void scan_kernel(int n) {
    __shared__ int wsum[32];
    __shared__ int s_carry;
    const int tid = threadIdx.x, lane = tid & 31, warp = tid >> 5;
    if (tid == 0) s_carry = 0;
    __syncthreads();
    for (int base = 0; base < n; base += 1024) {
        int i = base + tid;
        int v = (i < n) ? g_counts[i] : 0;
        int incl = v;
        #pragma unroll
        for (int o = 1; o < 32; o <<= 1) {
            int t = __shfl_up_sync(0xffffffffu, incl, o);
            if (lane >= o) incl += t;
        }
        if (lane == 31) wsum[warp] = incl;
        __syncthreads();
        if (warp == 0) {
            int s = wsum[lane];
            #pragma unroll
            for (int o = 1; o < 32; o <<= 1) {
                int t = __shfl_up_sync(0xffffffffu, s, o);
                if (lane >= o) s += t;
            }
            wsum[lane] = s;
        }
        __syncthreads();
        int excl = s_carry + (warp ? wsum[warp - 1] : 0) + incl - v;
        if (i < n) { g_rowptr[i] = excl; g_cursor[i] = excl; }
        int total = wsum[31];
        __syncthreads();
        if (tid == 0) s_carry += total;
        __syncthreads();
    }
    if (tid == 0) g_rowptr[n] = s_carry;
}

__global__ void fill_kernel(const int* __restrict__ ei,
                            const float* __restrict__ ew, int E, int n) {
    int e = blockIdx.x * blockDim.x + threadIdx.x;
    if (e >= E) return;
    int row = load_idx(ei, (size_t)e, n);
    int col = load_idx(ei, (size_t)E + e, n);
    int pos = atomicAdd(&g_cursor[col], 1);
    g_csr_src[pos] = row;
    g_csr_w[pos]   = ew[e] * g_dinv1[row];
}

// ---------------- tensor-core GEMM (bf16 3-term split, fp32 accumulate) ----------------
// C[M,N] = A[M,K] @ B[K,N]; fp32 in/out; N % 128 == 0, K % 32 == 0.
// Block 128x128x32, 256 threads, warp tile 64x32, mma.sync.m16n8k16.bf16.

__device__ __forceinline__ uint32_t sptr(const void* p) {
    return (uint32_t)__cvta_generic_to_shared(p);
}
__device__ __forceinline__ void ldsm_x4(uint32_t& r0, uint32_t& r1, uint32_t& r2,
                                        uint32_t& r3, uint32_t addr) {
    asm volatile("ldmatrix.sync.aligned.m8n8.x4.shared.b16 {%0,%1,%2,%3}, [%4];"
                 : "=r"(r0), "=r"(r1), "=r"(r2), "=r"(r3) : "r"(addr));
}
__device__ __forceinline__ void ldsm_x2t(uint32_t& r0, uint32_t& r1, uint32_t addr) {
    asm volatile("ldmatrix.sync.aligned.m8n8.x2.trans.shared.b16 {%0,%1}, [%2];"
                 : "=r"(r0), "=r"(r1) : "r"(addr));
}
__device__ __forceinline__ void mma_bf16(float* c, const uint32_t* a, const uint32_t* b) {
    asm volatile("mma.sync.aligned.m16n8k16.row.col.f32.bf16.bf16.f32 "
                 "{%0,%1,%2,%3}, {%4,%5,%6,%7}, {%8,%9}, {%0,%1,%2,%3};"
                 : "+f"(c[0]), "+f"(c[1]), "+f"(c[2]), "+f"(c[3])
                 : "r"(a[0]), "r"(a[1]), "r"(a[2]), "r"(a[3]),
                   "r"(b[0]), "r"(b[1]));
}
__device__ __forceinline__ void split2(float x, float y, __nv_bfloat162& hi, __nv_bfloat162& lo) {
    __nv_bfloat16 hx = __float2bfloat16(x);
    __nv_bfloat16 hy = __float2bfloat16(y);
    __nv_bfloat16 lx = __float2bfloat16(x - __bfloat162float(hx));
    __nv_bfloat16 ly = __float2bfloat16(y - __bfloat162float(hy));
    hi = __halves2bfloat162(hx, hy);
    lo = __halves2bfloat162(lx, ly);
}

__device__ __forceinline__ void bfgemm_body(const float* __restrict__ A,
                                            const float* __restrict__ B,
                                            float* __restrict__ C,
                                            int M, int N, int K) {
    __shared__ alignas(16) __nv_bfloat16 As[2][128][40];   // [hi/lo][BM][BK+8]
    __shared__ alignas(16) __nv_bfloat16 Bs[2][32][136];   // [hi/lo][BK][BN+8]
    const int t = threadIdx.x;
    const int lane = t & 31;
    const int warp = t >> 5;
    const int wm = (warp >> 2) * 64;
    const int wn = (warp & 3) * 32;
    const int rowTile = blockIdx.y * 128;
    const int colTile = blockIdx.x * 128;

    float acc[4][4][4];
    #pragma unroll
    for (int i = 0; i < 4; i++)
        #pragma unroll
        for (int j = 0; j < 4; j++)
            #pragma unroll
            for (int q = 0; q < 4; q++) acc[i][j][q] = 0.0f;

    for (int k0 = 0; k0 < K; k0 += 32) {
        __syncthreads();
        // A tile 128x32 fp32 -> bf16 hi/lo (coalesced float4 loads)
        #pragma unroll
        for (int i = 0; i < 4; i++) {
            int row = i * 32 + (t >> 3);
            int col = (t & 7) * 4;
            int gr = rowTile + row;
            float4 v = make_float4(0.f, 0.f, 0.f, 0.f);
            if (gr < M) v = *(const float4*)&A[(size_t)gr * K + k0 + col];
            __nv_bfloat162 h0, l0, h1, l1;
            split2(v.x, v.y, h0, l0);
            split2(v.z, v.w, h1, l1);
            *(__nv_bfloat162*)&As[0][row][col]     = h0;
            *(__nv_bfloat162*)&As[0][row][col + 2] = h1;
            *(__nv_bfloat162*)&As[1][row][col]     = l0;
            *(__nv_bfloat162*)&As[1][row][col + 2] = l1;
        }
        // B tile 32x128 fp32 -> bf16 hi/lo (coalesced float4 loads)
        #pragma unroll
        for (int i = 0; i < 4; i++) {
            int row = i * 8 + (t >> 5);
            int col = (t & 31) * 4;
            float4 v = *(const float4*)&B[(size_t)(k0 + row) * N + colTile + col];
            __nv_bfloat162 h0, l0, h1, l1;
            split2(v.x, v.y, h0, l0);
            split2(v.z, v.w, h1, l1);
            *(__nv_bfloat162*)&Bs[0][row][col]     = h0;
            *(__nv_bfloat162*)&Bs[0][row][col + 2] = h1;
            *(__nv_bfloat162*)&Bs[1][row][col]     = l0;
            *(__nv_bfloat162*)&Bs[1][row][col + 2] = l1;
        }
        __syncthreads();

        #pragma unroll
        for (int kk = 0; kk < 2; kk++) {
            const int kt = kk * 16;
            uint32_t ah[4][4], al[4][4], bh[4][2], bl[4][2];
            #pragma unroll
            for (int mt = 0; mt < 4; mt++) {
                int r = wm + mt * 16 + (lane & 15);
                int c = kt + ((lane >> 4) << 3);
                ldsm_x4(ah[mt][0], ah[mt][1], ah[mt][2], ah[mt][3], sptr(&As[0][r][c]));
                ldsm_x4(al[mt][0], al[mt][1], al[mt][2], al[mt][3], sptr(&As[1][r][c]));
            }
            #pragma unroll
            for (int nt = 0; nt < 4; nt++) {
                int r = kt + (lane & 15);
                int c = wn + nt * 8;
                ldsm_x2t(bh[nt][0], bh[nt][1], sptr(&Bs[0][r][c]));
                ldsm_x2t(bl[nt][0], bl[nt][1], sptr(&Bs[1][r][c]));
            }
            #pragma unroll
            for (int mt = 0; mt < 4; mt++)
                #pragma unroll
                for (int nt = 0; nt < 4; nt++) {
                    mma_bf16(acc[mt][nt], ah[mt], bh[nt]);
                    mma_bf16(acc[mt][nt], al[mt], bh[nt]);
                    mma_bf16(acc[mt][nt], ah[mt], bl[nt]);
                }
        }
    }

    // store C
    const int g = lane >> 2, tig = lane & 3;
    #pragma unroll
    for (int mt = 0; mt < 4; mt++) {
        #pragma unroll
        for (int nt = 0; nt < 4; nt++) {
            int row = rowTile + wm + mt * 16 + g;
            int col = colTile + wn + nt * 8 + tig * 2;
            if (row < M) {
                float2 v0 = make_float2(acc[mt][nt][0], acc[mt][nt][1]);
                *(float2*)&C[(size_t)row * N + col] = v0;
            }
            if (row + 8 < M) {
                float2 v1 = make_float2(acc[mt][nt][2], acc[mt][nt][3]);
                *(float2*)&C[(size_t)(row + 8) * N + col] = v1;
            }
        }
    }
}

// GEMM1: g_xw1 = node_attr @ W1
__global__ void __launch_bounds__(256, 1)
bfgemm1_kernel(const float* __restrict__ A, const float* __restrict__ B, int M) {
    bfgemm_body(A, B, &g_xw1[0], M, D2, D1);
}
// GEMM2: g_xw2 = g_h1 @ W2
__global__ void __launch_bounds__(256, 1)
bfgemm2_kernel(const float* __restrict__ B, int M) {
    bfgemm_body(&g_h1[0], B, &g_xw2[0], M, D3, D2);
}

// ---------------- layer-1 aggregation (block of 128 threads per destination node) ----------------
__global__ void aggregate1_kernel(const float* __restrict__ b1, int n) {
    const int j = blockIdx.x;
    const int tid = threadIdx.x;  // 128
    __shared__ int   s_src[128];
    __shared__ float s_w[128];
    const int start = g_rowptr[j];
    const int end   = g_rowptr[j + 1];
    float4 acc = make_float4(0.f, 0.f, 0.f, 0.f);
    for (int base = start; base < end; base += 128) {
        int ne = min(128, end - base);
        __syncthreads();
        if (tid < ne) { s_src[tid] = g_csr_src[base + tid]; s_w[tid] = g_csr_w[base + tid]; }
        __syncthreads();
        for (int i = 0; i < ne; i++) {
            const float4 v = *(const float4*)&g_xw1[(size_t)s_src[i] * D2 + tid * 4];
            const float w = s_w[i];
            acc.x = fmaf(w, v.x, acc.x);
            acc.y = fmaf(w, v.y, acc.y);
            acc.z = fmaf(w, v.z, acc.z);
            acc.w = fmaf(w, v.w, acc.w);
        }
    }
    const float di  = g_dinv1[j];
    const float di2 = di * di;
    const float4 sv = *(const float4*)&g_xw1[(size_t)j * D2 + tid * 4];
    const float4 bb = *(const float4*)&b1[tid * 4];
    float4 o;
    o.x = fmaxf(fmaf(di, acc.x, fmaf(di2, sv.x, bb.x)), 0.f);
    o.y = fmaxf(fmaf(di, acc.y, fmaf(di2, sv.y, bb.y)), 0.f);
    o.z = fmaxf(fmaf(di, acc.z, fmaf(di2, sv.z, bb.z)), 0.f);
    o.w = fmaxf(fmaf(di, acc.w, fmaf(di2, sv.w, bb.w)), 0.f);
    *(float4*)&g_h1[(size_t)j * D2 + tid * 4] = o;
}

// ---------------- per-node similarity projections ----------------
__global__ void sim_kernel(const float* __restrict__ Wm, int n) {
    const int gw = (blockIdx.x * blockDim.x + threadIdx.x) >> 5;
    const int lane = threadIdx.x & 31;
    if (gw >= n) return;
    const float* hr = &g_h1[0] + (size_t)gw * D2;
    float a = 0.f, b = 0.f;
    #pragma unroll 4
    for (int k = lane; k < D2; k += 32) {
        float h = hr[k];
        a = fmaf(h, Wm[k], a);
        b = fmaf(h, Wm[D2 + k], b);
    }
    #pragma unroll
    for (int o = 16; o; o >>= 1) {
        a += __shfl_down_sync(0xffffffffu, a, o);
        b += __shfl_down_sync(0xffffffffu, b, o);
    }
    if (lane == 0) { g_ssrc[gw] = a; g_sdst[gw] = b; }
}

// ---------------- deg2 / e2 (warp per destination node) ----------------
__global__ void deg2_kernel(const float* __restrict__ bm, int n) {
    const int j = (blockIdx.x * blockDim.x + threadIdx.x) >> 5;
    const int lane = threadIdx.x & 31;
    if (j >= n) return;
    const float sd = g_sdst[j] + bm[0];
    const int start = g_rowptr[j], end = g_rowptr[j + 1];
    float sum = 0.f;
    for (int e = start + lane; e < end; e += 32) {
        float e2 = fmaxf(g_ssrc[g_csr_src[e]] + sd, 0.f);
        g_csr_e2[e] = e2;
        sum += e2;
    }
    #pragma unroll
    for (int o = 16; o; o >>= 1) sum += __shfl_down_sync(0xffffffffu, sum, o);
    if (lane == 0) g_dinv2[j] = rsqrtf(1.0f + sum);
}

__global__ void w2_kernel(int E) {
    int e = blockIdx.x * blockDim.x + threadIdx.x;
    if (e < E) g_csr_e2[e] *= g_dinv2[g_csr_src[e]];
}

// ---------------- layer-2 aggregation (warp per node, 128 dims) ----------------
__global__ void aggregate2_kernel(const float* __restrict__ b2,
                                  float* __restrict__ out, int n) {
    const int j = (blockIdx.x * blockDim.x + threadIdx.x) >> 5;
    const int lane = threadIdx.x & 31;
    if (j >= n) return;
    const int start = g_rowptr[j], end = g_rowptr[j + 1];
    float4 acc = make_float4(0.f, 0.f, 0.f, 0.f);
    for (int e = start; e < end; e++) {
        int s = g_csr_src[e];
        float w = g_csr_e2[e];
        const float4 v = *(const float4*)&g_xw2[(size_t)s * D3 + lane * 4];
        acc.x = fmaf(w, v.x, acc.x);
        acc.y = fmaf(w, v.y, acc.y);
        acc.z = fmaf(w, v.z, acc.z);
        acc.w = fmaf(w, v.w, acc.w);
    }
    const float di = g_dinv2[j];
    const float di2 = di * di;
    const float4 sv = *(const float4*)&g_xw2[(size_t)j * D3 + lane * 4];
    const float4 bb = *(const float4*)&b2[lane * 4];
    float4 o;
    o.x = fmaf(di, acc.x, fmaf(di2, sv.x, bb.x));
    o.y = fmaf(di, acc.y, fmaf(di2, sv.y, bb.y));
    o.z = fmaf(di, acc.z, fmaf(di2, sv.z, bb.z));
    o.w = fmaf(di, acc.w, fmaf(di2, sv.w, bb.w));
    *(float4*)&out[(size_t)j * D3 + lane * 4] = o;
}

// ---------------- launch ----------------
extern "C" void kernel_launch(void* const* d_in, const int* in_sizes, int n_in,
                              void* d_out, int out_size) {
    const float* node_attr  = (const float*)d_in[0];
    const float* edge_attr  = (const float*)d_in[1];
    const int*   edge_index = (const int*)d_in[2];   // dtype auto-detected (int32/int64)
    const float* W1 = (const float*)d_in[5];
    const float* b1 = (const float*)d_in[6];
    const float* W2 = (const float*)d_in[7];
    const float* b2 = (const float*)d_in[8];
    const float* Wm = (const float*)d_in[9];
    const float* bm = (const float*)d_in[10];
    float* out = (float*)d_out;

    const int n = in_sizes[0] / D1;   // 100000
    const int E = in_sizes[1];        // 1600000

    const int TB = 256;
    detect_kernel<<<1, 32>>>(edge_index);
    init_nodes_kernel<<<(n + TB - 1) / TB, TB>>>(n);
    edge_count_kernel<<<(E + TB - 1) / TB, TB>>>(edge_index, edge_attr, E, n);
    dinv1_kernel<<<(n + TB - 1) / TB, TB>>>(n);
    scan_kernel<<<1, 1024>>>(n);
    fill_kernel<<<(E + TB - 1) / TB, TB>>>(edge_index, edge_attr, E, n);

    // GEMM1: xw1 = node_attr @ W1   [100000,1024]x[1024,512]  (tensor cores)
    {
        dim3 grid(D2 / 128, (n + 127) / 128);
        bfgemm1_kernel<<<grid, 256>>>(node_attr, W1, n);
    }
    aggregate1_kernel<<<n, 128>>>(b1, n);

    sim_kernel<<<(n * 32 + TB - 1) / TB, TB>>>(Wm, n);
    deg2_kernel<<<(n * 32 + TB - 1) / TB, TB>>>(bm, n);
    w2_kernel<<<(E + TB - 1) / TB, TB>>>(E);

    // GEMM2: xw2 = h1 @ W2  [100000,512]x[512,128]  (tensor cores)
    {
        dim3 grid(D3 / 128, (n + 127) / 128);
        bfgemm2_kernel<<<grid, 256>>>(W2, n);
    }
    aggregate2_kernel<<<(n * 32 + TB - 1) / TB, TB>>>(b2, out, n);
}

// round 7
// speedup vs baseline: 1.9900x; 1.2611x over previous
#include <cuda_runtime.h>
#include <cuda_bf16.h>
#include <cstdint>

// Problem constants (verified against reference setup_inputs)
#define NN 100000
#define NE 1600000
#define D1 1024
#define D2 512
#define D3 128

// ---------------- scratch (static __device__; referenced ONLY from device code) ----------------
__device__ float g_xw1[(size_t)NN * D2];    // node_attr @ W1
__device__ float g_h1 [(size_t)NN * D2];    // relu(gcn1)
__device__ float g_xw2[(size_t)NN * D3];    // h1 @ W2
__device__ float g_deg1[NN];
__device__ float g_dinv1[NN];
__device__ float g_dinv2[NN];
__device__ float g_ssrc[NN];
__device__ float g_sdst[NN];
__device__ int   g_counts[NN];
__device__ int   g_rowptr[NN + 1];
__device__ int   g_cursor[NN];
__device__ int   g_csr_src[NE];
__device__ float g_csr_w[NE];    // edge_weight * dinv1[src]
__device__ float g_csr_e2[NE];   // e2 (later scaled by dinv2[src] in-place)
__device__ int   g_is64;         // 1 if edge_index is int64 on device, else 0 (int32)

// ---------------- edge_index dtype detection ----------------
__global__ void detect_kernel(const int* __restrict__ ei32) {
    unsigned lane = threadIdx.x;
    int v = ei32[2 * lane + 1];
    unsigned b = __ballot_sync(0xffffffffu, v == 0);
    if (lane == 0) g_is64 = (b == 0xffffffffu) ? 1 : 0;
}

__device__ __forceinline__ int load_idx(const int* ei32, size_t pos, int n) {
    int v;
    if (g_is64) v = (int)((const long long*)ei32)[pos];
    else        v = ei32[pos];
    return min(max(v, 0), n - 1);
}

// ---------------- CSR construction ----------------
__global__ void init_nodes_kernel(int n) {
    int i = blockIdx.x * blockDim.x + threadIdx.x;
    if (i < n) { g_deg1[i] = 1.0f; g_counts[i] = 0; }
}

__global__ void edge_count_kernel(const int* __restrict__ ei,
                                  const float* __restrict__ ew, int E, int n) {
    int e = blockIdx.x * blockDim.x + threadIdx.x;
    if (e >= E) return;
    int col = load_idx(ei, (size_t)E + e, n);
    atomicAdd(&g_counts[col], 1);
    atomicAdd(&g_deg1[col], ew[e]);
}

__global__ void dinv1_kernel(int n) {
    int i = blockIdx.x * blockDim.x + threadIdx.x;
    if (i < n) {
        float d = g_deg1[i];
        g_dinv1[i] = (d > 0.0f) ? rsqrtf(d) : 0.0f;
    }
}

__global__ void scan_kernel(int n) {
    __shared__ int wsum[32];
    __shared__ int s_carry;
    const int tid = threadIdx.x, lane = tid & 31, warp = tid >> 5;
    if (tid == 0) s_carry = 0;
    __syncthreads();
    for (int base = 0; base < n; base += 1024) {
        int i = base + tid;
        int v = (i < n) ? g_counts[i] : 0;
        int incl = v;
        #pragma unroll
        for (int o = 1; o < 32; o <<= 1) {
            int t = __shfl_up_sync(0xffffffffu, incl, o);
            if (lane >= o) incl += t;
        }
        if (lane == 31) wsum[warp] = incl;
        __syncthreads();
        if (warp == 0) {
            int s = wsum[lane];
            #pragma unroll
            for (int o = 1; o < 32; o <<= 1) {
                int t = __shfl_up_sync(0xffffffffu, s, o);
                if (lane >= o) s += t;
            }
            wsum[lane] = s;
        }
        __syncthreads();
        int excl = s_carry + (warp ? wsum[warp - 1] : 0) + incl - v;
        if (i < n) { g_rowptr[i] = excl; g_cursor[i] = excl; }
        int total = wsum[31];
        __syncthreads();
        if (tid == 0) s_carry += total;
        __syncthreads();
    }
    if (tid == 0) g_rowptr[n] = s_carry;
}

__global__ void fill_kernel(const int* __restrict__ ei,
                            const float* __restrict__ ew, int E, int n) {
    int e = blockIdx.x * blockDim.x + threadIdx.x;
    if (e >= E) return;
    int row = load_idx(ei, (size_t)e, n);
    int col = load_idx(ei, (size_t)E + e, n);
    int pos = atomicAdd(&g_cursor[col], 1);
    g_csr_src[pos] = row;
    g_csr_w[pos]   = ew[e] * g_dinv1[row];
}

// ---------------- tensor-core GEMM (bf16 3-term split, fp32 accumulate) ----------------
// C[M,N] = A[M,K] @ B[K,N]; fp32 in/out; N % 128 == 0, K % 32 == 0.
// Block 128x128x32, 256 threads, warp tile 64x32, mma.sync.m16n8k16.bf16.
// Register-prefetch pipeline: iteration i+1's global loads are issued before
// iteration i's MMAs, hiding DRAM/L2 latency behind tensor work.

__device__ __forceinline__ uint32_t sptr(const void* p) {
    return (uint32_t)__cvta_generic_to_shared(p);
}
__device__ __forceinline__ void ldsm_x4(uint32_t& r0, uint32_t& r1, uint32_t& r2,
                                        uint32_t& r3, uint32_t addr) {
    asm volatile("ldmatrix.sync.aligned.m8n8.x4.shared.b16 {%0,%1,%2,%3}, [%4];"
                 : "=r"(r0), "=r"(r1), "=r"(r2), "=r"(r3) : "r"(addr));
}
__device__ __forceinline__ void ldsm_x2t(uint32_t& r0, uint32_t& r1, uint32_t addr) {
    asm volatile("ldmatrix.sync.aligned.m8n8.x2.trans.shared.b16 {%0,%1}, [%2];"
                 : "=r"(r0), "=r"(r1) : "r"(addr));
}
__device__ __forceinline__ void mma_bf16(float* c, const uint32_t* a, const uint32_t* b) {
    asm volatile("mma.sync.aligned.m16n8k16.row.col.f32.bf16.bf16.f32 "
                 "{%0,%1,%2,%3}, {%4,%5,%6,%7}, {%8,%9}, {%0,%1,%2,%3};"
                 : "+f"(c[0]), "+f"(c[1]), "+f"(c[2]), "+f"(c[3])
                 : "r"(a[0]), "r"(a[1]), "r"(a[2]), "r"(a[3]),
                   "r"(b[0]), "r"(b[1]));
}
__device__ __forceinline__ void split2(float x, float y, __nv_bfloat162& hi, __nv_bfloat162& lo) {
    __nv_bfloat16 hx = __float2bfloat16(x);
    __nv_bfloat16 hy = __float2bfloat16(y);
    __nv_bfloat16 lx = __float2bfloat16(x - __bfloat162float(hx));
    __nv_bfloat16 ly = __float2bfloat16(y - __bfloat162float(hy));
    hi = __halves2bfloat162(hx, hy);
    lo = __halves2bfloat162(lx, ly);
}

__device__ __forceinline__ void bfgemm_body(const float* __restrict__ A,
                                            const float* __restrict__ B,
                                            float* __restrict__ C,
                                            int M, int N, int K) {
    __shared__ alignas(16) __nv_bfloat16 As[2][128][40];   // [hi/lo][BM][BK+8]
    __shared__ alignas(16) __nv_bfloat16 Bs[2][32][136];   // [hi/lo][BK][BN+8]
    const int t = threadIdx.x;
    const int lane = t & 31;
    const int warp = t >> 5;
    const int wm = (warp >> 2) * 64;
    const int wn = (warp & 3) * 32;
    const int rowTile = blockIdx.y * 128;
    const int colTile = blockIdx.x * 128;

    // per-thread load coordinates
    const int aRow0 = t >> 3;           // +i*32
    const int aCol  = (t & 7) * 4;
    const int bRow0 = t >> 5;           // +i*8
    const int bCol  = (t & 31) * 4;

    float acc[4][4][4];
    #pragma unroll
    for (int i = 0; i < 4; i++)
        #pragma unroll
        for (int j = 0; j < 4; j++)
            #pragma unroll
            for (int q = 0; q < 4; q++) acc[i][j][q] = 0.0f;

    float4 pa[4], pb[4];
    // prefetch k0 = 0
    #pragma unroll
    for (int i = 0; i < 4; i++) {
        int gr = rowTile + aRow0 + i * 32;
        pa[i] = make_float4(0.f, 0.f, 0.f, 0.f);
        if (gr < M) pa[i] = *(const float4*)&A[(size_t)gr * K + aCol];
        pb[i] = *(const float4*)&B[(size_t)(bRow0 + i * 8) * N + colTile + bCol];
    }

    for (int k0 = 0; k0 < K; k0 += 32) {
        // convert + store the prefetched tile into smem
        #pragma unroll
        for (int i = 0; i < 4; i++) {
            int row = aRow0 + i * 32;
            __nv_bfloat162 h0, l0, h1, l1;
            split2(pa[i].x, pa[i].y, h0, l0);
            split2(pa[i].z, pa[i].w, h1, l1);
            *(__nv_bfloat162*)&As[0][row][aCol]     = h0;
            *(__nv_bfloat162*)&As[0][row][aCol + 2] = h1;
            *(__nv_bfloat162*)&As[1][row][aCol]     = l0;
            *(__nv_bfloat162*)&As[1][row][aCol + 2] = l1;
        }
        #pragma unroll
        for (int i = 0; i < 4; i++) {
            int row = bRow0 + i * 8;
            __nv_bfloat162 h0, l0, h1, l1;
            split2(pb[i].x, pb[i].y, h0, l0);
            split2(pb[i].z, pb[i].w, h1, l1);
            *(__nv_bfloat162*)&Bs[0][row][bCol]     = h0;
            *(__nv_bfloat162*)&Bs[0][row][bCol + 2] = h1;
            *(__nv_bfloat162*)&Bs[1][row][bCol]     = l0;
            *(__nv_bfloat162*)&Bs[1][row][bCol + 2] = l1;
        }
        __syncthreads();

        // issue next iteration's global loads NOW (latency hidden by MMAs below)
        if (k0 + 32 < K) {
            const int kn = k0 + 32;
            #pragma unroll
            for (int i = 0; i < 4; i++) {
                int gr = rowTile + aRow0 + i * 32;
                pa[i] = make_float4(0.f, 0.f, 0.f, 0.f);
                if (gr < M) pa[i] = *(const float4*)&A[(size_t)gr * K + kn + aCol];
                pb[i] = *(const float4*)&B[(size_t)(kn + bRow0 + i * 8) * N + colTile + bCol];
            }
        }

        #pragma unroll
        for (int kk = 0; kk < 2; kk++) {
            const int kt = kk * 16;
            uint32_t ah[4][4], al[4][4], bh[4][2], bl[4][2];
            #pragma unroll
            for (int mt = 0; mt < 4; mt++) {
                int r = wm + mt * 16 + (lane & 15);
                int c = kt + ((lane >> 4) << 3);
                ldsm_x4(ah[mt][0], ah[mt][1], ah[mt][2], ah[mt][3], sptr(&As[0][r][c]));
                ldsm_x4(al[mt][0], al[mt][1], al[mt][2], al[mt][3], sptr(&As[1][r][c]));
            }
            #pragma unroll
            for (int nt = 0; nt < 4; nt++) {
                int r = kt + (lane & 15);
                int c = wn + nt * 8;
                ldsm_x2t(bh[nt][0], bh[nt][1], sptr(&Bs[0][r][c]));
                ldsm_x2t(bl[nt][0], bl[nt][1], sptr(&Bs[1][r][c]));
            }
            #pragma unroll
            for (int mt = 0; mt < 4; mt++)
                #pragma unroll
                for (int nt = 0; nt < 4; nt++) {
                    mma_bf16(acc[mt][nt], ah[mt], bh[nt]);
                    mma_bf16(acc[mt][nt], al[mt], bh[nt]);
                    mma_bf16(acc[mt][nt], ah[mt], bl[nt]);
                }
        }
        __syncthreads();
    }

    // store C
    const int g = lane >> 2, tig = lane & 3;
    #pragma unroll
    for (int mt = 0; mt < 4; mt++) {
        #pragma unroll
        for (int nt = 0; nt < 4; nt++) {
            int row = rowTile + wm + mt * 16 + g;
            int col = colTile + wn + nt * 8 + tig * 2;
            if (row < M) {
                float2 v0 = make_float2(acc[mt][nt][0], acc[mt][nt][1]);
                *(float2*)&C[(size_t)row * N + col] = v0;
            }
            if (row + 8 < M) {
                float2 v1 = make_float2(acc[mt][nt][2], acc[mt][nt][3]);
                *(float2*)&C[(size_t)(row + 8) * N + col] = v1;
            }
        }
    }
}

// GEMM1: g_xw1 = node_attr @ W1
__global__ void __launch_bounds__(256, 1)
bfgemm1_kernel(const float* __restrict__ A, const float* __restrict__ B, int M) {
    bfgemm_body(A, B, &g_xw1[0], M, D2, D1);
}
// GEMM2: g_xw2 = g_h1 @ W2
__global__ void __launch_bounds__(256, 1)
bfgemm2_kernel(const float* __restrict__ B, int M) {
    bfgemm_body(&g_h1[0], B, &g_xw2[0], M, D3, D2);
}

// ---------------- layer-1 aggregation + fused similarity projections ----------------
// Block of 128 threads per destination node. After writing h1, compute
// ssrc = h1 . Wm[0:512] and sdst = h1 . Wm[512:1024] via block reduction.
__global__ void aggregate1_kernel(const float* __restrict__ b1,
                                  const float* __restrict__ Wm, int n) {
    const int j = blockIdx.x;
    const int tid = threadIdx.x;  // 128
    const int lane = tid & 31, warp = tid >> 5;
    __shared__ int   s_src[128];
    __shared__ float s_w[128];
    __shared__ float red[2][4];
    const int start = g_rowptr[j];
    const int end   = g_rowptr[j + 1];
    float4 acc = make_float4(0.f, 0.f, 0.f, 0.f);
    for (int base = start; base < end; base += 128) {
        int ne = min(128, end - base);
        __syncthreads();
        if (tid < ne) { s_src[tid] = g_csr_src[base + tid]; s_w[tid] = g_csr_w[base + tid]; }
        __syncthreads();
        for (int i = 0; i < ne; i++) {
            const float4 v = *(const float4*)&g_xw1[(size_t)s_src[i] * D2 + tid * 4];
            const float w = s_w[i];
            acc.x = fmaf(w, v.x, acc.x);
            acc.y = fmaf(w, v.y, acc.y);
            acc.z = fmaf(w, v.z, acc.z);
            acc.w = fmaf(w, v.w, acc.w);
        }
    }
    const float di  = g_dinv1[j];
    const float di2 = di * di;
    const float4 sv = *(const float4*)&g_xw1[(size_t)j * D2 + tid * 4];
    const float4 bb = *(const float4*)&b1[tid * 4];
    float4 o;
    o.x = fmaxf(fmaf(di, acc.x, fmaf(di2, sv.x, bb.x)), 0.f);
    o.y = fmaxf(fmaf(di, acc.y, fmaf(di2, sv.y, bb.y)), 0.f);
    o.z = fmaxf(fmaf(di, acc.z, fmaf(di2, sv.z, bb.z)), 0.f);
    o.w = fmaxf(fmaf(di, acc.w, fmaf(di2, sv.w, bb.w)), 0.f);
    *(float4*)&g_h1[(size_t)j * D2 + tid * 4] = o;

    // fused similarity projections
    const float4 wa = *(const float4*)&Wm[tid * 4];
    const float4 wb = *(const float4*)&Wm[D2 + tid * 4];
    float sa = o.x * wa.x + o.y * wa.y + o.z * wa.z + o.w * wa.w;
    float sb = o.x * wb.x + o.y * wb.y + o.z * wb.z + o.w * wb.w;
    #pragma unroll
    for (int off = 16; off; off >>= 1) {
        sa += __shfl_down_sync(0xffffffffu, sa, off);
        sb += __shfl_down_sync(0xffffffffu, sb, off);
    }
    if (lane == 0) { red[0][warp] = sa; red[1][warp] = sb; }
    __syncthreads();
    if (tid == 0) g_ssrc[j] = red[0][0] + red[0][1] + red[0][2] + red[0][3];
    if (tid == 1) g_sdst[j] = red[1][0] + red[1][1] + red[1][2] + red[1][3];
}

// ---------------- deg2 / e2 (warp per destination node) ----------------
__global__ void deg2_kernel(const float* __restrict__ bm, int n) {
    const int j = (blockIdx.x * blockDim.x + threadIdx.x) >> 5;
    const int lane = threadIdx.x & 31;
    if (j >= n) return;
    const float sd = g_sdst[j] + bm[0];
    const int start = g_rowptr[j], end = g_rowptr[j + 1];
    float sum = 0.f;
    for (int e = start + lane; e < end; e += 32) {
        float e2 = fmaxf(g_ssrc[g_csr_src[e]] + sd, 0.f);
        g_csr_e2[e] = e2;
        sum += e2;
    }
    #pragma unroll
    for (int o = 16; o; o >>= 1) sum += __shfl_down_sync(0xffffffffu, sum, o);
    if (lane == 0) g_dinv2[j] = rsqrtf(1.0f + sum);
}

__global__ void w2_kernel(int E) {
    int e = blockIdx.x * blockDim.x + threadIdx.x;
    if (e < E) g_csr_e2[e] *= g_dinv2[g_csr_src[e]];
}

// ---------------- layer-2 aggregation (warp per node, 128 dims) ----------------
__global__ void aggregate2_kernel(const float* __restrict__ b2,
                                  float* __restrict__ out, int n) {
    const int j = (blockIdx.x * blockDim.x + threadIdx.x) >> 5;
    const int lane = threadIdx.x & 31;
    if (j >= n) return;
    const int start = g_rowptr[j], end = g_rowptr[j + 1];
    float4 acc = make_float4(0.f, 0.f, 0.f, 0.f);
    for (int e = start; e < end; e++) {
        int s = g_csr_src[e];
        float w = g_csr_e2[e];
        const float4 v = *(const float4*)&g_xw2[(size_t)s * D3 + lane * 4];
        acc.x = fmaf(w, v.x, acc.x);
        acc.y = fmaf(w, v.y, acc.y);
        acc.z = fmaf(w, v.z, acc.z);
        acc.w = fmaf(w, v.w, acc.w);
    }
    const float di = g_dinv2[j];
    const float di2 = di * di;
    const float4 sv = *(const float4*)&g_xw2[(size_t)j * D3 + lane * 4];
    const float4 bb = *(const float4*)&b2[lane * 4];
    float4 o;
    o.x = fmaf(di, acc.x, fmaf(di2, sv.x, bb.x));
    o.y = fmaf(di, acc.y, fmaf(di2, sv.y, bb.y));
    o.z = fmaf(di, acc.z, fmaf(di2, sv.z, bb.z));
    o.w = fmaf(di, acc.w, fmaf(di2, sv.w, bb.w));
    *(float4*)&out[(size_t)j * D3 + lane * 4] = o;
}

// ---------------- launch ----------------
extern "C" void kernel_launch(void* const* d_in, const int* in_sizes, int n_in,
                              void* d_out, int out_size) {
    const float* node_attr  = (const float*)d_in[0];
    const float* edge_attr  = (const float*)d_in[1];
    const int*   edge_index = (const int*)d_in[2];   // dtype auto-detected (int32/int64)
    const float* W1 = (const float*)d_in[5];
    const float* b1 = (const float*)d_in[6];
    const float* W2 = (const float*)d_in[7];
    const float* b2 = (const float*)d_in[8];
    const float* Wm = (const float*)d_in[9];
    const float* bm = (const float*)d_in[10];
    float* out = (float*)d_out;

    const int n = in_sizes[0] / D1;   // 100000
    const int E = in_sizes[1];        // 1600000

    const int TB = 256;
    detect_kernel<<<1, 32>>>(edge_index);
    init_nodes_kernel<<<(n + TB - 1) / TB, TB>>>(n);
    edge_count_kernel<<<(E + TB - 1) / TB, TB>>>(edge_index, edge_attr, E, n);
    dinv1_kernel<<<(n + TB - 1) / TB, TB>>>(n);
    scan_kernel<<<1, 1024>>>(n);
    fill_kernel<<<(E + TB - 1) / TB, TB>>>(edge_index, edge_attr, E, n);

    // GEMM1: xw1 = node_attr @ W1   [100000,1024]x[1024,512]  (tensor cores, prefetch)
    {
        dim3 grid(D2 / 128, (n + 127) / 128);
        bfgemm1_kernel<<<grid, 256>>>(node_attr, W1, n);
    }
    // layer-1 aggregate + relu + fused similarity -> h1, ssrc, sdst
    aggregate1_kernel<<<n, 128>>>(b1, Wm, n);

    deg2_kernel<<<(n * 32 + TB - 1) / TB, TB>>>(bm, n);
    w2_kernel<<<(E + TB - 1) / TB, TB>>>(E);

    // GEMM2: xw2 = h1 @ W2  [100000,512]x[512,128]  (tensor cores, prefetch)
    {
        dim3 grid(D3 / 128, (n + 127) / 128);
        bfgemm2_kernel<<<grid, 256>>>(W2, n);
    }
    aggregate2_kernel<<<(n * 32 + TB - 1) / TB, TB>>>(b2, out, n);
}

// round 8
// speedup vs baseline: 2.1220x; 1.0664x over previous
#include <cuda_runtime.h>
#include <cuda_bf16.h>
#include <cstdint>

// Problem constants (verified against reference setup_inputs)
#define NN 100000
#define NE 1600000
#define D1 1024
#define D2 512
#define D3 128

// ---------------- scratch (static __device__; referenced ONLY from device code) ----------------
__device__ float g_xw1[(size_t)NN * D2];    // node_attr @ W1
__device__ float g_h1 [(size_t)NN * D2];    // relu(gcn1)
__device__ float g_xw2[(size_t)NN * D3];    // h1 @ W2
__device__ float g_deg1[NN];
__device__ float g_dinv1[NN];
__device__ float g_dinv2[NN];
__device__ float g_ssrc[NN];
__device__ float g_sdst[NN];
__device__ int   g_counts[NN];
__device__ int   g_rowptr[NN + 1];
__device__ int   g_cursor[NN];
__device__ int   g_csr_src[NE];
__device__ float g_csr_w[NE];    // edge_weight * dinv1[src]
__device__ int   g_is64;         // 1 if edge_index is int64 on device, else 0 (int32)
// pre-converted weights (bf16 hi/lo split)
__device__ __nv_bfloat16 g_w1hi[D1 * D2];
__device__ __nv_bfloat16 g_w1lo[D1 * D2];
__device__ __nv_bfloat16 g_w2hi[D2 * D3];
__device__ __nv_bfloat16 g_w2lo[D2 * D3];

// ---------------- edge_index dtype detection ----------------
__global__ void detect_kernel(const int* __restrict__ ei32) {
    unsigned lane = threadIdx.x;
    int v = ei32[2 * lane + 1];
    unsigned b = __ballot_sync(0xffffffffu, v == 0);
    if (lane == 0) g_is64 = (b == 0xffffffffu) ? 1 : 0;
}

__device__ __forceinline__ int load_idx(const int* ei32, size_t pos, int n) {
    int v;
    if (g_is64) v = (int)((const long long*)ei32)[pos];
    else        v = ei32[pos];
    return min(max(v, 0), n - 1);
}

// ---------------- weight pre-conversion ----------------
__global__ void wconv1_kernel(const float* __restrict__ W) {
    int i = blockIdx.x * blockDim.x + threadIdx.x;
    if (i < D1 * D2) {
        float x = W[i];
        __nv_bfloat16 h = __float2bfloat16(x);
        g_w1hi[i] = h;
        g_w1lo[i] = __float2bfloat16(x - __bfloat162float(h));
    }
}
__global__ void wconv2_kernel(const float* __restrict__ W) {
    int i = blockIdx.x * blockDim.x + threadIdx.x;
    if (i < D2 * D3) {
        float x = W[i];
        __nv_bfloat16 h = __float2bfloat16(x);
        g_w2hi[i] = h;
        g_w2lo[i] = __float2bfloat16(x - __bfloat162float(h));
    }
}

// ---------------- CSR construction ----------------
__global__ void init_nodes_kernel(int n) {
    int i = blockIdx.x * blockDim.x + threadIdx.x;
    if (i < n) { g_deg1[i] = 1.0f; g_counts[i] = 0; }
}

__global__ void edge_count_kernel(const int* __restrict__ ei,
                                  const float* __restrict__ ew, int E, int n) {
    int e = blockIdx.x * blockDim.x + threadIdx.x;
    if (e >= E) return;
    int col = load_idx(ei, (size_t)E + e, n);
    atomicAdd(&g_counts[col], 1);
    atomicAdd(&g_deg1[col], ew[e]);
}

__global__ void dinv1_kernel(int n) {
    int i = blockIdx.x * blockDim.x + threadIdx.x;
    if (i < n) {
        float d = g_deg1[i];
        g_dinv1[i] = (d > 0.0f) ? rsqrtf(d) : 0.0f;
    }
}

__global__ void scan_kernel(int n) {
    __shared__ int wsum[32];
    __shared__ int s_carry;
    const int tid = threadIdx.x, lane = tid & 31, warp = tid >> 5;
    if (tid == 0) s_carry = 0;
    __syncthreads();
    for (int base = 0; base < n; base += 1024) {
        int i = base + tid;
        int v = (i < n) ? g_counts[i] : 0;
        int incl = v;
        #pragma unroll
        for (int o = 1; o < 32; o <<= 1) {
            int t = __shfl_up_sync(0xffffffffu, incl, o);
            if (lane >= o) incl += t;
        }
        if (lane == 31) wsum[warp] = incl;
        __syncthreads();
        if (warp == 0) {
            int s = wsum[lane];
            #pragma unroll
            for (int o = 1; o < 32; o <<= 1) {
                int t = __shfl_up_sync(0xffffffffu, s, o);
                if (lane >= o) s += t;
            }
            wsum[lane] = s;
        }
        __syncthreads();
        int excl = s_carry + (warp ? wsum[warp - 1] : 0) + incl - v;
        if (i < n) { g_rowptr[i] = excl; g_cursor[i] = excl; }
        int total = wsum[31];
        __syncthreads();
        if (tid == 0) s_carry += total;
        __syncthreads();
    }
    if (tid == 0) g_rowptr[n] = s_carry;
}

__global__ void fill_kernel(const int* __restrict__ ei,
                            const float* __restrict__ ew, int E, int n) {
    int e = blockIdx.x * blockDim.x + threadIdx.x;
    if (e >= E) return;
    int row = load_idx(ei, (size_t)e, n);
    int col = load_idx(ei, (size_t)E + e, n);
    int pos = atomicAdd(&g_cursor[col], 1);
    g_csr_src[pos] = row;
    g_csr_w[pos]   = ew[e] * g_dinv1[row];
}

// ---------------- tensor-core GEMM (bf16 3-term split, fp32 accumulate) ----------------
// C[M,N] = A[M,K] @ B[K,N]; A fp32, B pre-split bf16 hi/lo; N % 128 == 0, K % 32 == 0.
// Block 128x128x32, 256 threads, warp tile 64x32, mma.sync.m16n8k16.bf16.
// Register-prefetch + ping-pong smem double buffering (one sync per k-iter).

#define SMEM_GEMM_BYTES (4 * 128 * 40 * 2 + 4 * 32 * 136 * 2)   // 40960 + 34816 = 75776

__device__ __forceinline__ uint32_t sptr(const void* p) {
    return (uint32_t)__cvta_generic_to_shared(p);
}
__device__ __forceinline__ void ldsm_x4(uint32_t& r0, uint32_t& r1, uint32_t& r2,
                                        uint32_t& r3, uint32_t addr) {
    asm volatile("ldmatrix.sync.aligned.m8n8.x4.shared.b16 {%0,%1,%2,%3}, [%4];"
                 : "=r"(r0), "=r"(r1), "=r"(r2), "=r"(r3) : "r"(addr));
}
__device__ __forceinline__ void ldsm_x2t(uint32_t& r0, uint32_t& r1, uint32_t addr) {
    asm volatile("ldmatrix.sync.aligned.m8n8.x2.trans.shared.b16 {%0,%1}, [%2];"
                 : "=r"(r0), "=r"(r1) : "r"(addr));
}
__device__ __forceinline__ void mma_bf16(float* c, const uint32_t* a, const uint32_t* b) {
    asm volatile("mma.sync.aligned.m16n8k16.row.col.f32.bf16.bf16.f32 "
                 "{%0,%1,%2,%3}, {%4,%5,%6,%7}, {%8,%9}, {%0,%1,%2,%3};"
                 : "+f"(c[0]), "+f"(c[1]), "+f"(c[2]), "+f"(c[3])
                 : "r"(a[0]), "r"(a[1]), "r"(a[2]), "r"(a[3]),
                   "r"(b[0]), "r"(b[1]));
}
__device__ __forceinline__ void split2(float x, float y, __nv_bfloat162& hi, __nv_bfloat162& lo) {
    __nv_bfloat16 hx = __float2bfloat16(x);
    __nv_bfloat16 hy = __float2bfloat16(y);
    __nv_bfloat16 lx = __float2bfloat16(x - __bfloat162float(hx));
    __nv_bfloat16 ly = __float2bfloat16(y - __bfloat162float(hy));
    hi = __halves2bfloat162(hx, hy);
    lo = __halves2bfloat162(lx, ly);
}

__device__ __forceinline__ void bfgemm_body(const float* __restrict__ A,
                                            const __nv_bfloat16* __restrict__ Bhi,
                                            const __nv_bfloat16* __restrict__ Blo,
                                            float* __restrict__ C,
                                            int M, int N, int K) {
    extern __shared__ __align__(16) char dyn_smem[];
    // As[buf][hl][128][40], Bs[buf][hl][32][136]
    typedef __nv_bfloat16 (*AsT)[2][128][40];
    typedef __nv_bfloat16 (*BsT)[2][32][136];
    AsT As = (AsT)dyn_smem;
    BsT Bs = (BsT)(dyn_smem + 4 * 128 * 40 * 2);

    const int t = threadIdx.x;
    const int lane = t & 31;
    const int warp = t >> 5;
    const int wm = (warp >> 2) * 64;
    const int wn = (warp & 3) * 32;
    const int rowTile = blockIdx.y * 128;
    const int colTile = blockIdx.x * 128;

    // per-thread load coordinates
    const int aRow0 = t >> 3;            // +i*32
    const int aCol  = (t & 7) * 4;
    const int bRow0 = t >> 4;            // +i*16
    const int bCol  = (t & 15) * 8;      // bf16 elements

    float acc[4][4][4];
    #pragma unroll
    for (int i = 0; i < 4; i++)
        #pragma unroll
        for (int j = 0; j < 4; j++)
            #pragma unroll
            for (int q = 0; q < 4; q++) acc[i][j][q] = 0.0f;

    float4 pa[4];
    uint4  pbh[2], pbl[2];

    // prefetch k0 = 0
    #pragma unroll
    for (int i = 0; i < 4; i++) {
        int gr = rowTile + aRow0 + i * 32;
        pa[i] = make_float4(0.f, 0.f, 0.f, 0.f);
        if (gr < M) pa[i] = *(const float4*)&A[(size_t)gr * K + aCol];
    }
    #pragma unroll
    for (int i = 0; i < 2; i++) {
        size_t off = (size_t)(bRow0 + i * 16) * N + colTile + bCol;
        pbh[i] = *(const uint4*)&Bhi[off];
        pbl[i] = *(const uint4*)&Blo[off];
    }

    // store tile 0 into buf 0
    #pragma unroll
    for (int i = 0; i < 4; i++) {
        int row = aRow0 + i * 32;
        __nv_bfloat162 h0, l0, h1, l1;
        split2(pa[i].x, pa[i].y, h0, l0);
        split2(pa[i].z, pa[i].w, h1, l1);
        *(__nv_bfloat162*)&As[0][0][row][aCol]     = h0;
        *(__nv_bfloat162*)&As[0][0][row][aCol + 2] = h1;
        *(__nv_bfloat162*)&As[0][1][row][aCol]     = l0;
        *(__nv_bfloat162*)&As[0][1][row][aCol + 2] = l1;
    }
    #pragma unroll
    for (int i = 0; i < 2; i++) {
        int row = bRow0 + i * 16;
        *(uint4*)&Bs[0][0][row][bCol] = pbh[i];
        *(uint4*)&Bs[0][1][row][bCol] = pbl[i];
    }
    __syncthreads();

    const int nk = K / 32;
    for (int it = 0; it < nk; it++) {
        const int buf = it & 1;
        // issue next tile's global loads (latency hidden behind MMAs)
        if (it + 1 < nk) {
            const int kn = (it + 1) * 32;
            #pragma unroll
            for (int i = 0; i < 4; i++) {
                int gr = rowTile + aRow0 + i * 32;
                pa[i] = make_float4(0.f, 0.f, 0.f, 0.f);
                if (gr < M) pa[i] = *(const float4*)&A[(size_t)gr * K + kn + aCol];
            }
            #pragma unroll
            for (int i = 0; i < 2; i++) {
                size_t off = (size_t)(kn + bRow0 + i * 16) * N + colTile + bCol;
                pbh[i] = *(const uint4*)&Bhi[off];
                pbl[i] = *(const uint4*)&Blo[off];
            }
        }

        // MMAs on current buffer
        #pragma unroll
        for (int kk = 0; kk < 2; kk++) {
            const int kt = kk * 16;
            uint32_t ah[4][4], al[4][4], bh[4][2], bl[4][2];
            #pragma unroll
            for (int mt = 0; mt < 4; mt++) {
                int r = wm + mt * 16 + (lane & 15);
                int c = kt + ((lane >> 4) << 3);
                ldsm_x4(ah[mt][0], ah[mt][1], ah[mt][2], ah[mt][3], sptr(&As[buf][0][r][c]));
                ldsm_x4(al[mt][0], al[mt][1], al[mt][2], al[mt][3], sptr(&As[buf][1][r][c]));
            }
            #pragma unroll
            for (int nt = 0; nt < 4; nt++) {
                int r = kt + (lane & 15);
                int c = wn + nt * 8;
                ldsm_x2t(bh[nt][0], bh[nt][1], sptr(&Bs[buf][0][r][c]));
                ldsm_x2t(bl[nt][0], bl[nt][1], sptr(&Bs[buf][1][r][c]));
            }
            #pragma unroll
            for (int mt = 0; mt < 4; mt++)
                #pragma unroll
                for (int nt = 0; nt < 4; nt++) {
                    mma_bf16(acc[mt][nt], ah[mt], bh[nt]);
                    mma_bf16(acc[mt][nt], al[mt], bh[nt]);
                    mma_bf16(acc[mt][nt], ah[mt], bl[nt]);
                }
        }

        // store next tile into the other buffer, single sync per iteration
        if (it + 1 < nk) {
            const int nb = buf ^ 1;
            #pragma unroll
            for (int i = 0; i < 4; i++) {
                int row = aRow0 + i * 32;
                __nv_bfloat162 h0, l0, h1, l1;
                split2(pa[i].x, pa[i].y, h0, l0);
                split2(pa[i].z, pa[i].w, h1, l1);
                *(__nv_bfloat162*)&As[nb][0][row][aCol]     = h0;
                *(__nv_bfloat162*)&As[nb][0][row][aCol + 2] = h1;
                *(__nv_bfloat162*)&As[nb][1][row][aCol]     = l0;
                *(__nv_bfloat162*)&As[nb][1][row][aCol + 2] = l1;
            }
            #pragma unroll
            for (int i = 0; i < 2; i++) {
                int row = bRow0 + i * 16;
                *(uint4*)&Bs[nb][0][row][bCol] = pbh[i];
                *(uint4*)&Bs[nb][1][row][bCol] = pbl[i];
            }
            __syncthreads();
        }
    }

    // store C
    const int g = lane >> 2, tig = lane & 3;
    #pragma unroll
    for (int mt = 0; mt < 4; mt++) {
        #pragma unroll
        for (int nt = 0; nt < 4; nt++) {
            int row = rowTile + wm + mt * 16 + g;
            int col = colTile + wn + nt * 8 + tig * 2;
            if (row < M) {
                float2 v0 = make_float2(acc[mt][nt][0], acc[mt][nt][1]);
                *(float2*)&C[(size_t)row * N + col] = v0;
            }
            if (row + 8 < M) {
                float2 v1 = make_float2(acc[mt][nt][2], acc[mt][nt][3]);
                *(float2*)&C[(size_t)(row + 8) * N + col] = v1;
            }
        }
    }
}

// GEMM1: g_xw1 = node_attr @ W1
__global__ void __launch_bounds__(256, 1)
bfgemm1_kernel(const float* __restrict__ A, int M) {
    bfgemm_body(A, &g_w1hi[0], &g_w1lo[0], &g_xw1[0], M, D2, D1);
}
// GEMM2: g_xw2 = g_h1 @ W2
__global__ void __launch_bounds__(256, 1)
bfgemm2_kernel(int M) {
    bfgemm_body(&g_h1[0], &g_w2hi[0], &g_w2lo[0], &g_xw2[0], M, D3, D2);
}

// ---------------- layer-1 aggregation + fused similarity projections ----------------
__global__ void aggregate1_kernel(const float* __restrict__ b1,
                                  const float* __restrict__ Wm, int n) {
    const int j = blockIdx.x;
    const int tid = threadIdx.x;  // 128
    const int lane = tid & 31, warp = tid >> 5;
    __shared__ int   s_src[128];
    __shared__ float s_w[128];
    __shared__ float red[2][4];
    const int start = g_rowptr[j];
    const int end   = g_rowptr[j + 1];
    float4 acc = make_float4(0.f, 0.f, 0.f, 0.f);
    for (int base = start; base < end; base += 128) {
        int ne = min(128, end - base);
        __syncthreads();
        if (tid < ne) { s_src[tid] = g_csr_src[base + tid]; s_w[tid] = g_csr_w[base + tid]; }
        __syncthreads();
        for (int i = 0; i < ne; i++) {
            const float4 v = *(const float4*)&g_xw1[(size_t)s_src[i] * D2 + tid * 4];
            const float w = s_w[i];
            acc.x = fmaf(w, v.x, acc.x);
            acc.y = fmaf(w, v.y, acc.y);
            acc.z = fmaf(w, v.z, acc.z);
            acc.w = fmaf(w, v.w, acc.w);
        }
    }
    const float di  = g_dinv1[j];
    const float di2 = di * di;
    const float4 sv = *(const float4*)&g_xw1[(size_t)j * D2 + tid * 4];
    const float4 bb = *(const float4*)&b1[tid * 4];
    float4 o;
    o.x = fmaxf(fmaf(di, acc.x, fmaf(di2, sv.x, bb.x)), 0.f);
    o.y = fmaxf(fmaf(di, acc.y, fmaf(di2, sv.y, bb.y)), 0.f);
    o.z = fmaxf(fmaf(di, acc.z, fmaf(di2, sv.z, bb.z)), 0.f);
    o.w = fmaxf(fmaf(di, acc.w, fmaf(di2, sv.w, bb.w)), 0.f);
    *(float4*)&g_h1[(size_t)j * D2 + tid * 4] = o;

    // fused similarity projections
    const float4 wa = *(const float4*)&Wm[tid * 4];
    const float4 wb = *(const float4*)&Wm[D2 + tid * 4];
    float sa = o.x * wa.x + o.y * wa.y + o.z * wa.z + o.w * wa.w;
    float sb = o.x * wb.x + o.y * wb.y + o.z * wb.z + o.w * wb.w;
    #pragma unroll
    for (int off = 16; off; off >>= 1) {
        sa += __shfl_down_sync(0xffffffffu, sa, off);
        sb += __shfl_down_sync(0xffffffffu, sb, off);
    }
    if (lane == 0) { red[0][warp] = sa; red[1][warp] = sb; }
    __syncthreads();
    if (tid == 0) g_ssrc[j] = red[0][0] + red[0][1] + red[0][2] + red[0][3];
    if (tid == 1) g_sdst[j] = red[1][0] + red[1][1] + red[1][2] + red[1][3];
}

// ---------------- deg2 (warp per destination node; produces dinv2 only) ----------------
__global__ void deg2_kernel(const float* __restrict__ bm, int n) {
    const int j = (blockIdx.x * blockDim.x + threadIdx.x) >> 5;
    const int lane = threadIdx.x & 31;
    if (j >= n) return;
    const float sd = g_sdst[j] + bm[0];
    const int start = g_rowptr[j], end = g_rowptr[j + 1];
    float sum = 0.f;
    for (int e = start + lane; e < end; e += 32) {
        sum += fmaxf(g_ssrc[g_csr_src[e]] + sd, 0.f);
    }
    #pragma unroll
    for (int o = 16; o; o >>= 1) sum += __shfl_down_sync(0xffffffffu, sum, o);
    if (lane == 0) g_dinv2[j] = rsqrtf(1.0f + sum);
}

// ---------------- layer-2 aggregation (warp per node; e2 recomputed on the fly) ----------------
__global__ void aggregate2_kernel(const float* __restrict__ b2,
                                  const float* __restrict__ bm,
                                  float* __restrict__ out, int n) {
    const int j = (blockIdx.x * blockDim.x + threadIdx.x) >> 5;
    const int lane = threadIdx.x & 31;
    if (j >= n) return;
    const float sd = g_sdst[j] + bm[0];
    const int start = g_rowptr[j], end = g_rowptr[j + 1];
    float4 acc = make_float4(0.f, 0.f, 0.f, 0.f);
    for (int e = start; e < end; e++) {
        int s = g_csr_src[e];
        float w = fmaxf(g_ssrc[s] + sd, 0.f) * g_dinv2[s];
        const float4 v = *(const float4*)&g_xw2[(size_t)s * D3 + lane * 4];
        acc.x = fmaf(w, v.x, acc.x);
        acc.y = fmaf(w, v.y, acc.y);
        acc.z = fmaf(w, v.z, acc.z);
        acc.w = fmaf(w, v.w, acc.w);
    }
    const float di = g_dinv2[j];
    const float di2 = di * di;
    const float4 sv = *(const float4*)&g_xw2[(size_t)j * D3 + lane * 4];
    const float4 bb = *(const float4*)&b2[lane * 4];
    float4 o;
    o.x = fmaf(di, acc.x, fmaf(di2, sv.x, bb.x));
    o.y = fmaf(di, acc.y, fmaf(di2, sv.y, bb.y));
    o.z = fmaf(di, acc.z, fmaf(di2, sv.z, bb.z));
    o.w = fmaf(di, acc.w, fmaf(di2, sv.w, bb.w));
    *(float4*)&out[(size_t)j * D3 + lane * 4] = o;
}

// ---------------- launch ----------------
extern "C" void kernel_launch(void* const* d_in, const int* in_sizes, int n_in,
                              void* d_out, int out_size) {
    const float* node_attr  = (const float*)d_in[0];
    const float* edge_attr  = (const float*)d_in[1];
    const int*   edge_index = (const int*)d_in[2];   // dtype auto-detected (int32/int64)
    const float* W1 = (const float*)d_in[5];
    const float* b1 = (const float*)d_in[6];
    const float* W2 = (const float*)d_in[7];
    const float* b2 = (const float*)d_in[8];
    const float* Wm = (const float*)d_in[9];
    const float* bm = (const float*)d_in[10];
    float* out = (float*)d_out;

    const int n = in_sizes[0] / D1;   // 100000
    const int E = in_sizes[1];        // 1600000

    cudaFuncSetAttribute(bfgemm1_kernel, cudaFuncAttributeMaxDynamicSharedMemorySize, SMEM_GEMM_BYTES);
    cudaFuncSetAttribute(bfgemm2_kernel, cudaFuncAttributeMaxDynamicSharedMemorySize, SMEM_GEMM_BYTES);

    const int TB = 256;
    detect_kernel<<<1, 32>>>(edge_index);
    wconv1_kernel<<<(D1 * D2 + TB - 1) / TB, TB>>>(W1);
    wconv2_kernel<<<(D2 * D3 + TB - 1) / TB, TB>>>(W2);
    init_nodes_kernel<<<(n + TB - 1) / TB, TB>>>(n);
    edge_count_kernel<<<(E + TB - 1) / TB, TB>>>(edge_index, edge_attr, E, n);
    dinv1_kernel<<<(n + TB - 1) / TB, TB>>>(n);
    scan_kernel<<<1, 1024>>>(n);
    fill_kernel<<<(E + TB - 1) / TB, TB>>>(edge_index, edge_attr, E, n);

    // GEMM1: xw1 = node_attr @ W1   [100000,1024]x[1024,512]
    {
        dim3 grid(D2 / 128, (n + 127) / 128);
        bfgemm1_kernel<<<grid, 256, SMEM_GEMM_BYTES>>>(node_attr, n);
    }
    // layer-1 aggregate + relu + fused similarity -> h1, ssrc, sdst
    aggregate1_kernel<<<n, 128>>>(b1, Wm, n);

    deg2_kernel<<<(n * 32 + TB - 1) / TB, TB>>>(bm, n);

    // GEMM2: xw2 = h1 @ W2  [100000,512]x[512,128]
    {
        dim3 grid(D3 / 128, (n + 127) / 128);
        bfgemm2_kernel<<<grid, 256, SMEM_GEMM_BYTES>>>(n);
    }
    aggregate2_kernel<<<(n * 32 + TB - 1) / TB, TB>>>(b2, bm, out, n);
}

// round 9
// speedup vs baseline: 2.4213x; 1.1410x over previous
#include <cuda_runtime.h>
#include <cuda_bf16.h>
#include <cuda_fp16.h>
#include <cstdint>

// Problem constants (verified against reference setup_inputs)
#define NN 100000
#define NE 1600000
#define D1 1024
#define D2 512
#define D3 128

// ---------------- scratch (static __device__; referenced ONLY from device code) ----------------
__device__ __half g_xw1h[(size_t)NN * D2];  // node_attr @ W1 (fp16)
__device__ float  g_h1 [(size_t)NN * D2];   // relu(gcn1) (fp32: feeds GEMM2 bf16 split)
__device__ __half g_xw2h[(size_t)NN * D3];  // h1 @ W2 (fp16)
__device__ float g_deg1[NN];
__device__ float g_dinv1[NN];
__device__ float g_dinv2[NN];
__device__ float g_ssrc[NN];
__device__ float g_sdst[NN];
__device__ int   g_counts[NN];
__device__ int   g_rowptr[NN + 1];
__device__ int   g_cursor[NN];
__device__ int   g_csr_src[NE];
__device__ float g_csr_w[NE];    // edge_weight * dinv1[src]
__device__ int   g_is64;         // 1 if edge_index is int64 on device, else 0 (int32)
// pre-converted weights (bf16 hi/lo split)
__device__ __nv_bfloat16 g_w1hi[D1 * D2];
__device__ __nv_bfloat16 g_w1lo[D1 * D2];
__device__ __nv_bfloat16 g_w2hi[D2 * D3];
__device__ __nv_bfloat16 g_w2lo[D2 * D3];

// ---------------- edge_index dtype detection ----------------
__global__ void detect_kernel(const int* __restrict__ ei32) {
    unsigned lane = threadIdx.x;
    int v = ei32[2 * lane + 1];
    unsigned b = __ballot_sync(0xffffffffu, v == 0);
    if (lane == 0) g_is64 = (b == 0xffffffffu) ? 1 : 0;
}

__device__ __forceinline__ int load_idx(const int* ei32, size_t pos, int n) {
    int v;
    if (g_is64) v = (int)((const long long*)ei32)[pos];
    else        v = ei32[pos];
    return min(max(v, 0), n - 1);
}

// ---------------- weight pre-conversion ----------------
__global__ void wconv1_kernel(const float* __restrict__ W) {
    int i = blockIdx.x * blockDim.x + threadIdx.x;
    if (i < D1 * D2) {
        float x = W[i];
        __nv_bfloat16 h = __float2bfloat16(x);
        g_w1hi[i] = h;
        g_w1lo[i] = __float2bfloat16(x - __bfloat162float(h));
    }
}
__global__ void wconv2_kernel(const float* __restrict__ W) {
    int i = blockIdx.x * blockDim.x + threadIdx.x;
    if (i < D2 * D3) {
        float x = W[i];
        __nv_bfloat16 h = __float2bfloat16(x);
        g_w2hi[i] = h;
        g_w2lo[i] = __float2bfloat16(x - __bfloat162float(h));
    }
}

// ---------------- CSR construction ----------------
__global__ void init_nodes_kernel(int n) {
    int i = blockIdx.x * blockDim.x + threadIdx.x;
    if (i < n) { g_deg1[i] = 1.0f; g_counts[i] = 0; }
}

__global__ void edge_count_kernel(const int* __restrict__ ei,
                                  const float* __restrict__ ew, int E, int n) {
    int e = blockIdx.x * blockDim.x + threadIdx.x;
    if (e >= E) return;
    int col = load_idx(ei, (size_t)E + e, n);
    atomicAdd(&g_counts[col], 1);
    atomicAdd(&g_deg1[col], ew[e]);
}

__global__ void dinv1_kernel(int n) {
    int i = blockIdx.x * blockDim.x + threadIdx.x;
    if (i < n) {
        float d = g_deg1[i];
        g_dinv1[i] = (d > 0.0f) ? rsqrtf(d) : 0.0f;
    }
}

__global__ void scan_kernel(int n) {
    __shared__ int wsum[32];
    __shared__ int s_carry;
    const int tid = threadIdx.x, lane = tid & 31, warp = tid >> 5;
    if (tid == 0) s_carry = 0;
    __syncthreads();
    for (int base = 0; base < n; base += 1024) {
        int i = base + tid;
        int v = (i < n) ? g_counts[i] : 0;
        int incl = v;
        #pragma unroll
        for (int o = 1; o < 32; o <<= 1) {
            int t = __shfl_up_sync(0xffffffffu, incl, o);
            if (lane >= o) incl += t;
        }
        if (lane == 31) wsum[warp] = incl;
        __syncthreads();
        if (warp == 0) {
            int s = wsum[lane];
            #pragma unroll
            for (int o = 1; o < 32; o <<= 1) {
                int t = __shfl_up_sync(0xffffffffu, s, o);
                if (lane >= o) s += t;
            }
            wsum[lane] = s;
        }
        __syncthreads();
        int excl = s_carry + (warp ? wsum[warp - 1] : 0) + incl - v;
        if (i < n) { g_rowptr[i] = excl; g_cursor[i] = excl; }
        int total = wsum[31];
        __syncthreads();
        if (tid == 0) s_carry += total;
        __syncthreads();
    }
    if (tid == 0) g_rowptr[n] = s_carry;
}

__global__ void fill_kernel(const int* __restrict__ ei,
                            const float* __restrict__ ew, int E, int n) {
    int e = blockIdx.x * blockDim.x + threadIdx.x;
    if (e >= E) return;
    int row = load_idx(ei, (size_t)e, n);
    int col = load_idx(ei, (size_t)E + e, n);
    int pos = atomicAdd(&g_cursor[col], 1);
    g_csr_src[pos] = row;
    g_csr_w[pos]   = ew[e] * g_dinv1[row];
}

// ---------------- tensor-core GEMM (bf16 3-term split, fp32 accumulate, fp16 out) ----------------
// C[M,N] = A[M,K] @ B[K,N]; A fp32, B pre-split bf16 hi/lo; C fp16; N%128==0, K%32==0.
// Block 128x128x32, 256 threads, warp tile 64x32, mma.sync.m16n8k16.bf16.
// Register-prefetch + ping-pong smem double buffering (one sync per k-iter).

#define SMEM_GEMM_BYTES (4 * 128 * 40 * 2 + 4 * 32 * 136 * 2)   // 40960 + 34816 = 75776

__device__ __forceinline__ uint32_t sptr(const void* p) {
    return (uint32_t)__cvta_generic_to_shared(p);
}
__device__ __forceinline__ void ldsm_x4(uint32_t& r0, uint32_t& r1, uint32_t& r2,
                                        uint32_t& r3, uint32_t addr) {
    asm volatile("ldmatrix.sync.aligned.m8n8.x4.shared.b16 {%0,%1,%2,%3}, [%4];"
                 : "=r"(r0), "=r"(r1), "=r"(r2), "=r"(r3) : "r"(addr));
}
__device__ __forceinline__ void ldsm_x2t(uint32_t& r0, uint32_t& r1, uint32_t addr) {
    asm volatile("ldmatrix.sync.aligned.m8n8.x2.trans.shared.b16 {%0,%1}, [%2];"
                 : "=r"(r0), "=r"(r1) : "r"(addr));
}
__device__ __forceinline__ void mma_bf16(float* c, const uint32_t* a, const uint32_t* b) {
    asm volatile("mma.sync.aligned.m16n8k16.row.col.f32.bf16.bf16.f32 "
                 "{%0,%1,%2,%3}, {%4,%5,%6,%7}, {%8,%9}, {%0,%1,%2,%3};"
                 : "+f"(c[0]), "+f"(c[1]), "+f"(c[2]), "+f"(c[3])
                 : "r"(a[0]), "r"(a[1]), "r"(a[2]), "r"(a[3]),
                   "r"(b[0]), "r"(b[1]));
}
__device__ __forceinline__ void split2(float x, float y, __nv_bfloat162& hi, __nv_bfloat162& lo) {
    __nv_bfloat16 hx = __float2bfloat16(x);
    __nv_bfloat16 hy = __float2bfloat16(y);
    __nv_bfloat16 lx = __float2bfloat16(x - __bfloat162float(hx));
    __nv_bfloat16 ly = __float2bfloat16(y - __bfloat162float(hy));
    hi = __halves2bfloat162(hx, hy);
    lo = __halves2bfloat162(lx, ly);
}

__device__ __forceinline__ void bfgemm_body(const float* __restrict__ A,
                                            const __nv_bfloat16* __restrict__ Bhi,
                                            const __nv_bfloat16* __restrict__ Blo,
                                            __half* __restrict__ C,
                                            int M, int N, int K) {
    extern __shared__ __align__(16) char dyn_smem[];
    typedef __nv_bfloat16 (*AsT)[2][128][40];
    typedef __nv_bfloat16 (*BsT)[2][32][136];
    AsT As = (AsT)dyn_smem;
    BsT Bs = (BsT)(dyn_smem + 4 * 128 * 40 * 2);

    const int t = threadIdx.x;
    const int lane = t & 31;
    const int warp = t >> 5;
    const int wm = (warp >> 2) * 64;
    const int wn = (warp & 3) * 32;
    const int rowTile = blockIdx.y * 128;
    const int colTile = blockIdx.x * 128;

    const int aRow0 = t >> 3;            // +i*32
    const int aCol  = (t & 7) * 4;
    const int bRow0 = t >> 4;            // +i*16
    const int bCol  = (t & 15) * 8;      // bf16 elements

    float acc[4][4][4];
    #pragma unroll
    for (int i = 0; i < 4; i++)
        #pragma unroll
        for (int j = 0; j < 4; j++)
            #pragma unroll
            for (int q = 0; q < 4; q++) acc[i][j][q] = 0.0f;

    float4 pa[4];
    uint4  pbh[2], pbl[2];

    // prefetch k0 = 0
    #pragma unroll
    for (int i = 0; i < 4; i++) {
        int gr = rowTile + aRow0 + i * 32;
        pa[i] = make_float4(0.f, 0.f, 0.f, 0.f);
        if (gr < M) pa[i] = *(const float4*)&A[(size_t)gr * K + aCol];
    }
    #pragma unroll
    for (int i = 0; i < 2; i++) {
        size_t off = (size_t)(bRow0 + i * 16) * N + colTile + bCol;
        pbh[i] = *(const uint4*)&Bhi[off];
        pbl[i] = *(const uint4*)&Blo[off];
    }

    // store tile 0 into buf 0
    #pragma unroll
    for (int i = 0; i < 4; i++) {
        int row = aRow0 + i * 32;
        __nv_bfloat162 h0, l0, h1, l1;
        split2(pa[i].x, pa[i].y, h0, l0);
        split2(pa[i].z, pa[i].w, h1, l1);
        *(__nv_bfloat162*)&As[0][0][row][aCol]     = h0;
        *(__nv_bfloat162*)&As[0][0][row][aCol + 2] = h1;
        *(__nv_bfloat162*)&As[0][1][row][aCol]     = l0;
        *(__nv_bfloat162*)&As[0][1][row][aCol + 2] = l1;
    }
    #pragma unroll
    for (int i = 0; i < 2; i++) {
        int row = bRow0 + i * 16;
        *(uint4*)&Bs[0][0][row][bCol] = pbh[i];
        *(uint4*)&Bs[0][1][row][bCol] = pbl[i];
    }
    __syncthreads();

    const int nk = K / 32;
    for (int it = 0; it < nk; it++) {
        const int buf = it & 1;
        if (it + 1 < nk) {
            const int kn = (it + 1) * 32;
            #pragma unroll
            for (int i = 0; i < 4; i++) {
                int gr = rowTile + aRow0 + i * 32;
                pa[i] = make_float4(0.f, 0.f, 0.f, 0.f);
                if (gr < M) pa[i] = *(const float4*)&A[(size_t)gr * K + kn + aCol];
            }
            #pragma unroll
            for (int i = 0; i < 2; i++) {
                size_t off = (size_t)(kn + bRow0 + i * 16) * N + colTile + bCol;
                pbh[i] = *(const uint4*)&Bhi[off];
                pbl[i] = *(const uint4*)&Blo[off];
            }
        }

        #pragma unroll
        for (int kk = 0; kk < 2; kk++) {
            const int kt = kk * 16;
            uint32_t ah[4][4], al[4][4], bh[4][2], bl[4][2];
            #pragma unroll
            for (int mt = 0; mt < 4; mt++) {
                int r = wm + mt * 16 + (lane & 15);
                int c = kt + ((lane >> 4) << 3);
                ldsm_x4(ah[mt][0], ah[mt][1], ah[mt][2], ah[mt][3], sptr(&As[buf][0][r][c]));
                ldsm_x4(al[mt][0], al[mt][1], al[mt][2], al[mt][3], sptr(&As[buf][1][r][c]));
            }
            #pragma unroll
            for (int nt = 0; nt < 4; nt++) {
                int r = kt + (lane & 15);
                int c = wn + nt * 8;
                ldsm_x2t(bh[nt][0], bh[nt][1], sptr(&Bs[buf][0][r][c]));
                ldsm_x2t(bl[nt][0], bl[nt][1], sptr(&Bs[buf][1][r][c]));
            }
            #pragma unroll
            for (int mt = 0; mt < 4; mt++)
                #pragma unroll
                for (int nt = 0; nt < 4; nt++) {
                    mma_bf16(acc[mt][nt], ah[mt], bh[nt]);
                    mma_bf16(acc[mt][nt], al[mt], bh[nt]);
                    mma_bf16(acc[mt][nt], ah[mt], bl[nt]);
                }
        }

        if (it + 1 < nk) {
            const int nb = buf ^ 1;
            #pragma unroll
            for (int i = 0; i < 4; i++) {
                int row = aRow0 + i * 32;
                __nv_bfloat162 h0, l0, h1, l1;
                split2(pa[i].x, pa[i].y, h0, l0);
                split2(pa[i].z, pa[i].w, h1, l1);
                *(__nv_bfloat162*)&As[nb][0][row][aCol]     = h0;
                *(__nv_bfloat162*)&As[nb][0][row][aCol + 2] = h1;
                *(__nv_bfloat162*)&As[nb][1][row][aCol]     = l0;
                *(__nv_bfloat162*)&As[nb][1][row][aCol + 2] = l1;
            }
            #pragma unroll
            for (int i = 0; i < 2; i++) {
                int row = bRow0 + i * 16;
                *(uint4*)&Bs[nb][0][row][bCol] = pbh[i];
                *(uint4*)&Bs[nb][1][row][bCol] = pbl[i];
            }
            __syncthreads();
        }
    }

    // store C as fp16
    const int g = lane >> 2, tig = lane & 3;
    #pragma unroll
    for (int mt = 0; mt < 4; mt++) {
        #pragma unroll
        for (int nt = 0; nt < 4; nt++) {
            int row = rowTile + wm + mt * 16 + g;
            int col = colTile + wn + nt * 8 + tig * 2;
            if (row < M) {
                *(__half2*)&C[(size_t)row * N + col] =
                    __floats2half2_rn(acc[mt][nt][0], acc[mt][nt][1]);
            }
            if (row + 8 < M) {
                *(__half2*)&C[(size_t)(row + 8) * N + col] =
                    __floats2half2_rn(acc[mt][nt][2], acc[mt][nt][3]);
            }
        }
    }
}

// GEMM1: g_xw1h = node_attr @ W1
__global__ void __launch_bounds__(256, 1)
bfgemm1_kernel(const float* __restrict__ A, int M) {
    bfgemm_body(A, &g_w1hi[0], &g_w1lo[0], &g_xw1h[0], M, D2, D1);
}
// GEMM2: g_xw2h = g_h1 @ W2
__global__ void __launch_bounds__(256, 1)
bfgemm2_kernel(int M) {
    bfgemm_body(&g_h1[0], &g_w2hi[0], &g_w2lo[0], &g_xw2h[0], M, D3, D2);
}

// ---------------- layer-1 aggregation + fused similarity projections ----------------
// Block of 128 threads per destination node; xw1 gathered in fp16 (half traffic),
// accumulation in fp32.
__global__ void aggregate1_kernel(const float* __restrict__ b1,
                                  const float* __restrict__ Wm, int n) {
    const int j = blockIdx.x;
    const int tid = threadIdx.x;  // 128
    const int lane = tid & 31, warp = tid >> 5;
    __shared__ int   s_src[128];
    __shared__ float s_w[128];
    __shared__ float red[2][4];
    const int start = g_rowptr[j];
    const int end   = g_rowptr[j + 1];
    float4 acc = make_float4(0.f, 0.f, 0.f, 0.f);
    for (int base = start; base < end; base += 128) {
        int ne = min(128, end - base);
        __syncthreads();
        if (tid < ne) { s_src[tid] = g_csr_src[base + tid]; s_w[tid] = g_csr_w[base + tid]; }
        __syncthreads();
        for (int i = 0; i < ne; i++) {
            const uint2 raw = *(const uint2*)&g_xw1h[(size_t)s_src[i] * D2 + tid * 4];
            const float2 v01 = __half22float2(*(const __half2*)&raw.x);
            const float2 v23 = __half22float2(*(const __half2*)&raw.y);
            const float w = s_w[i];
            acc.x = fmaf(w, v01.x, acc.x);
            acc.y = fmaf(w, v01.y, acc.y);
            acc.z = fmaf(w, v23.x, acc.z);
            acc.w = fmaf(w, v23.y, acc.w);
        }
    }
    const float di  = g_dinv1[j];
    const float di2 = di * di;
    const uint2 sraw = *(const uint2*)&g_xw1h[(size_t)j * D2 + tid * 4];
    const float2 s01 = __half22float2(*(const __half2*)&sraw.x);
    const float2 s23 = __half22float2(*(const __half2*)&sraw.y);
    const float4 bb = *(const float4*)&b1[tid * 4];
    float4 o;
    o.x = fmaxf(fmaf(di, acc.x, fmaf(di2, s01.x, bb.x)), 0.f);
    o.y = fmaxf(fmaf(di, acc.y, fmaf(di2, s01.y, bb.y)), 0.f);
    o.z = fmaxf(fmaf(di, acc.z, fmaf(di2, s23.x, bb.z)), 0.f);
    o.w = fmaxf(fmaf(di, acc.w, fmaf(di2, s23.y, bb.w)), 0.f);
    *(float4*)&g_h1[(size_t)j * D2 + tid * 4] = o;

    // fused similarity projections
    const float4 wa = *(const float4*)&Wm[tid * 4];
    const float4 wb = *(const float4*)&Wm[D2 + tid * 4];
    float sa = o.x * wa.x + o.y * wa.y + o.z * wa.z + o.w * wa.w;
    float sb = o.x * wb.x + o.y * wb.y + o.z * wb.z + o.w * wb.w;
    #pragma unroll
    for (int off = 16; off; off >>= 1) {
        sa += __shfl_down_sync(0xffffffffu, sa, off);
        sb += __shfl_down_sync(0xffffffffu, sb, off);
    }
    if (lane == 0) { red[0][warp] = sa; red[1][warp] = sb; }
    __syncthreads();
    if (tid == 0) g_ssrc[j] = red[0][0] + red[0][1] + red[0][2] + red[0][3];
    if (tid == 1) g_sdst[j] = red[1][0] + red[1][1] + red[1][2] + red[1][3];
}

// ---------------- deg2 (warp per destination node; produces dinv2 only) ----------------
__global__ void deg2_kernel(const float* __restrict__ bm, int n) {
    const int j = (blockIdx.x * blockDim.x + threadIdx.x) >> 5;
    const int lane = threadIdx.x & 31;
    if (j >= n) return;
    const float sd = g_sdst[j] + bm[0];
    const int start = g_rowptr[j], end = g_rowptr[j + 1];
    float sum = 0.f;
    for (int e = start + lane; e < end; e += 32) {
        sum += fmaxf(g_ssrc[g_csr_src[e]] + sd, 0.f);
    }
    #pragma unroll
    for (int o = 16; o; o >>= 1) sum += __shfl_down_sync(0xffffffffu, sum, o);
    if (lane == 0) g_dinv2[j] = rsqrtf(1.0f + sum);
}

// ---------------- layer-2 aggregation (warp per node; e2 recomputed; xw2 in fp16) ----------------
__global__ void aggregate2_kernel(const float* __restrict__ b2,
                                  const float* __restrict__ bm,
                                  float* __restrict__ out, int n) {
    const int j = (blockIdx.x * blockDim.x + threadIdx.x) >> 5;
    const int lane = threadIdx.x & 31;
    if (j >= n) return;
    const float sd = g_sdst[j] + bm[0];
    const int start = g_rowptr[j], end = g_rowptr[j + 1];
    float4 acc = make_float4(0.f, 0.f, 0.f, 0.f);
    for (int e = start; e < end; e++) {
        int s = g_csr_src[e];
        float w = fmaxf(g_ssrc[s] + sd, 0.f) * g_dinv2[s];
        const uint2 raw = *(const uint2*)&g_xw2h[(size_t)s * D3 + lane * 4];
        const float2 v01 = __half22float2(*(const __half2*)&raw.x);
        const float2 v23 = __half22float2(*(const __half2*)&raw.y);
        acc.x = fmaf(w, v01.x, acc.x);
        acc.y = fmaf(w, v01.y, acc.y);
        acc.z = fmaf(w, v23.x, acc.z);
        acc.w = fmaf(w, v23.y, acc.w);
    }
    const float di = g_dinv2[j];
    const float di2 = di * di;
    const uint2 sraw = *(const uint2*)&g_xw2h[(size_t)j * D3 + lane * 4];
    const float2 s01 = __half22float2(*(const __half2*)&sraw.x);
    const float2 s23 = __half22float2(*(const __half2*)&sraw.y);
    const float4 bb = *(const float4*)&b2[lane * 4];
    float4 o;
    o.x = fmaf(di, acc.x, fmaf(di2, s01.x, bb.x));
    o.y = fmaf(di, acc.y, fmaf(di2, s01.y, bb.y));
    o.z = fmaf(di, acc.z, fmaf(di2, s23.x, bb.z));
    o.w = fmaf(di, acc.w, fmaf(di2, s23.y, bb.w));
    *(float4*)&out[(size_t)j * D3 + lane * 4] = o;
}

// ---------------- launch ----------------
extern "C" void kernel_launch(void* const* d_in, const int* in_sizes, int n_in,
                              void* d_out, int out_size) {
    const float* node_attr  = (const float*)d_in[0];
    const float* edge_attr  = (const float*)d_in[1];
    const int*   edge_index = (const int*)d_in[2];   // dtype auto-detected (int32/int64)
    const float* W1 = (const float*)d_in[5];
    const float* b1 = (const float*)d_in[6];
    const float* W2 = (const float*)d_in[7];
    const float* b2 = (const float*)d_in[8];
    const float* Wm = (const float*)d_in[9];
    const float* bm = (const float*)d_in[10];
    float* out = (float*)d_out;

    const int n = in_sizes[0] / D1;   // 100000
    const int E = in_sizes[1];        // 1600000

    cudaFuncSetAttribute(bfgemm1_kernel, cudaFuncAttributeMaxDynamicSharedMemorySize, SMEM_GEMM_BYTES);
    cudaFuncSetAttribute(bfgemm2_kernel, cudaFuncAttributeMaxDynamicSharedMemorySize, SMEM_GEMM_BYTES);

    const int TB = 256;
    detect_kernel<<<1, 32>>>(edge_index);
    wconv1_kernel<<<(D1 * D2 + TB - 1) / TB, TB>>>(W1);
    wconv2_kernel<<<(D2 * D3 + TB - 1) / TB, TB>>>(W2);
    init_nodes_kernel<<<(n + TB - 1) / TB, TB>>>(n);
    edge_count_kernel<<<(E + TB - 1) / TB, TB>>>(edge_index, edge_attr, E, n);
    dinv1_kernel<<<(n + TB - 1) / TB, TB>>>(n);
    scan_kernel<<<1, 1024>>>(n);
    fill_kernel<<<(E + TB - 1) / TB, TB>>>(edge_index, edge_attr, E, n);

    // GEMM1: xw1 = node_attr @ W1   [100000,1024]x[1024,512] -> fp16
    {
        dim3 grid(D2 / 128, (n + 127) / 128);
        bfgemm1_kernel<<<grid, 256, SMEM_GEMM_BYTES>>>(node_attr, n);
    }
    // layer-1 aggregate + relu + fused similarity -> h1 (fp32), ssrc, sdst
    aggregate1_kernel<<<n, 128>>>(b1, Wm, n);

    deg2_kernel<<<(n * 32 + TB - 1) / TB, TB>>>(bm, n);

    // GEMM2: xw2 = h1 @ W2  [100000,512]x[512,128] -> fp16
    {
        dim3 grid(D3 / 128, (n + 127) / 128);
        bfgemm2_kernel<<<grid, 256, SMEM_GEMM_BYTES>>>(n);
    }
    aggregate2_kernel<<<(n * 32 + TB - 1) / TB, TB>>>(b2, bm, out, n);
}

// round 12
// speedup vs baseline: 2.4794x; 1.0240x over previous
#include <cuda_runtime.h>
#include <cuda_bf16.h>
#include <cuda_fp16.h>
#include <cstdint>

// Problem constants (verified against reference setup_inputs)
#define NN 100000
#define NE 1600000
#define D1 1024
#define D2 512
#define D3 128

// ---------------- scratch (static __device__; referenced ONLY from device code) ----------------
__device__ __half g_xw1h[(size_t)NN * D2];  // node_attr @ W1 (fp16)
__device__ float  g_h1 [(size_t)NN * D2];   // relu(gcn1) (fp32: feeds GEMM2 bf16 split)
__device__ __half g_xw2h[(size_t)NN * D3];  // h1 @ W2 (fp16)
__device__ float g_deg1[NN];
__device__ float g_dinv1[NN];
__device__ float g_dinv2[NN];
__device__ float g_ssrc[NN];
__device__ float g_sdst[NN];
__device__ int   g_counts[NN];
__device__ int   g_rowptr[NN + 1];
__device__ int   g_cursor[NN];
__device__ int   g_csr_src[NE];
__device__ float g_csr_w[NE];    // edge_weight * dinv1[src]
__device__ int   g_is64;         // 1 if edge_index is int64 on device, else 0 (int32)
// pre-converted weights (bf16 hi/lo split)
__device__ __nv_bfloat16 g_w1hi[D1 * D2];
__device__ __nv_bfloat16 g_w1lo[D1 * D2];
__device__ __nv_bfloat16 g_w2hi[D2 * D3];
__device__ __nv_bfloat16 g_w2lo[D2 * D3];

// ---------------- edge_index dtype detection ----------------
__global__ void detect_kernel(const int* __restrict__ ei32) {
    unsigned lane = threadIdx.x;
    int v = ei32[2 * lane + 1];
    unsigned b = __ballot_sync(0xffffffffu, v == 0);
    if (lane == 0) g_is64 = (b == 0xffffffffu) ? 1 : 0;
}

__device__ __forceinline__ int load_idx(const int* ei32, size_t pos, int n) {
    int v;
    if (g_is64) v = (int)((const long long*)ei32)[pos];
    else        v = ei32[pos];
    return min(max(v, 0), n - 1);
}

// ---------------- weight pre-conversion ----------------
__global__ void wconv1_kernel(const float* __restrict__ W) {
    int i = blockIdx.x * blockDim.x + threadIdx.x;
    if (i < D1 * D2) {
        float x = W[i];
        __nv_bfloat16 h = __float2bfloat16(x);
        g_w1hi[i] = h;
        g_w1lo[i] = __float2bfloat16(x - __bfloat162float(h));
    }
}
__global__ void wconv2_kernel(const float* __restrict__ W) {
    int i = blockIdx.x * blockDim.x + threadIdx.x;
    if (i < D2 * D3) {
        float x = W[i];
        __nv_bfloat16 h = __float2bfloat16(x);
        g_w2hi[i] = h;
        g_w2lo[i] = __float2bfloat16(x - __bfloat162float(h));
    }
}

// ---------------- CSR construction ----------------
__global__ void init_nodes_kernel(int n) {
    int i = blockIdx.x * blockDim.x + threadIdx.x;
    if (i < n) { g_deg1[i] = 1.0f; g_counts[i] = 0; }
}

__global__ void edge_count_kernel(const int* __restrict__ ei,
                                  const float* __restrict__ ew, int E, int n) {
    int e = blockIdx.x * blockDim.x + threadIdx.x;
    if (e >= E) return;
    int col = load_idx(ei, (size_t)E + e, n);
    atomicAdd(&g_counts[col], 1);
    atomicAdd(&g_deg1[col], ew[e]);
}

__global__ void dinv1_kernel(int n) {
    int i = blockIdx.x * blockDim.x + threadIdx.x;
    if (i < n) {
        float d = g_deg1[i];
        g_dinv1[i] = (d > 0.0f) ? rsqrtf(d) : 0.0f;
    }
}

__global__ void scan_kernel(int n) {
    __shared__ int wsum[32];
    __shared__ int s_carry;
    const int tid = threadIdx.x, lane = tid & 31, warp = tid >> 5;
    if (tid == 0) s_carry = 0;
    __syncthreads();
    for (int base = 0; base < n; base += 1024) {
        int i = base + tid;
        int v = (i < n) ? g_counts[i] : 0;
        int incl = v;
        #pragma unroll
        for (int o = 1; o < 32; o <<= 1) {
            int t = __shfl_up_sync(0xffffffffu, incl, o);
            if (lane >= o) incl += t;
        }
        if (lane == 31) wsum[warp] = incl;
        __syncthreads();
        if (warp == 0) {
            int s = wsum[lane];
            #pragma unroll
            for (int o = 1; o < 32; o <<= 1) {
                int t = __shfl_up_sync(0xffffffffu, s, o);
                if (lane >= o) s += t;
            }
            wsum[lane] = s;
        }
        __syncthreads();
        int excl = s_carry + (warp ? wsum[warp - 1] : 0) + incl - v;
        if (i < n) { g_rowptr[i] = excl; g_cursor[i] = excl; }
        int total = wsum[31];
        __syncthreads();
        if (tid == 0) s_carry += total;
        __syncthreads();
    }
    if (tid == 0) g_rowptr[n] = s_carry;
}

__global__ void fill_kernel(const int* __restrict__ ei,
                            const float* __restrict__ ew, int E, int n) {
    int e = blockIdx.x * blockDim.x + threadIdx.x;
    if (e >= E) return;
    int row = load_idx(ei, (size_t)e, n);
    int col = load_idx(ei, (size_t)E + e, n);
    int pos = atomicAdd(&g_cursor[col], 1);
    g_csr_src[pos] = row;
    g_csr_w[pos]   = ew[e] * g_dinv1[row];
}

// ---------------- tensor-core GEMM (bf16 3-term split, fp32 accumulate, fp16 out) ----------------
#define SMEM_GEMM_BYTES (4 * 128 * 40 * 2 + 4 * 32 * 136 * 2)   // 75776

__device__ __forceinline__ uint32_t sptr(const void* p) {
    return (uint32_t)__cvta_generic_to_shared(p);
}
__device__ __forceinline__ void ldsm_x4(uint32_t& r0, uint32_t& r1, uint32_t& r2,
                                        uint32_t& r3, uint32_t addr) {
    asm volatile("ldmatrix.sync.aligned.m8n8.x4.shared.b16 {%0,%1,%2,%3}, [%4];"
                 : "=r"(r0), "=r"(r1), "=r"(r2), "=r"(r3) : "r"(addr));
}
__device__ __forceinline__ void ldsm_x2t(uint32_t& r0, uint32_t& r1, uint32_t addr) {
    asm volatile("ldmatrix.sync.aligned.m8n8.x2.trans.shared.b16 {%0,%1}, [%2];"
                 : "=r"(r0), "=r"(r1) : "r"(addr));
}
__device__ __forceinline__ void mma_bf16(float* c, const uint32_t* a, const uint32_t* b) {
    asm volatile("mma.sync.aligned.m16n8k16.row.col.f32.bf16.bf16.f32 "
                 "{%0,%1,%2,%3}, {%4,%5,%6,%7}, {%8,%9}, {%0,%1,%2,%3};"
                 : "+f"(c[0]), "+f"(c[1]), "+f"(c[2]), "+f"(c[3])
                 : "r"(a[0]), "r"(a[1]), "r"(a[2]), "r"(a[3]),
                   "r"(b[0]), "r"(b[1]));
}
__device__ __forceinline__ void split2(float x, float y, __nv_bfloat162& hi, __nv_bfloat162& lo) {
    __nv_bfloat16 hx = __float2bfloat16(x);
    __nv_bfloat16 hy = __float2bfloat16(y);
    __nv_bfloat16 lx = __float2bfloat16(x - __bfloat162float(hx));
    __nv_bfloat16 ly = __float2bfloat16(y - __bfloat162float(hy));
    hi = __halves2bfloat162(hx, hy);
    lo = __halves2bfloat162(lx, ly);
}

__device__ __forceinline__ void bfgemm_body(const float* __restrict__ A,
                                            const __nv_bfloat16* __restrict__ Bhi,
                                            const __nv_bfloat16* __restrict__ Blo,
                                            __half* __restrict__ C,
                                            int M, int N, int K) {
    extern __shared__ __align__(16) char dyn_smem[];
    typedef __nv_bfloat16 (*AsT)[2][128][40];
    typedef __nv_bfloat16 (*BsT)[2][32][136];
    AsT As = (AsT)dyn_smem;
    BsT Bs = (BsT)(dyn_smem + 4 * 128 * 40 * 2);

    const int t = threadIdx.x;
    const int lane = t & 31;
    const int warp = t >> 5;
    const int wm = (warp >> 2) * 64;
    const int wn = (warp & 3) * 32;
    const int rowTile = blockIdx.y * 128;
    const int colTile = blockIdx.x * 128;

    const int aRow0 = t >> 3;            // +i*32
    const int aCol  = (t & 7) * 4;
    const int bRow0 = t >> 4;            // +i*16
    const int bCol  = (t & 15) * 8;      // bf16 elements

    float acc[4][4][4];
    #pragma unroll
    for (int i = 0; i < 4; i++)
        #pragma unroll
        for (int j = 0; j < 4; j++)
            #pragma unroll
            for (int q = 0; q < 4; q++) acc[i][j][q] = 0.0f;

    float4 pa[4];
    uint4  pbh[2], pbl[2];

    #pragma unroll
    for (int i = 0; i < 4; i++) {
        int gr = rowTile + aRow0 + i * 32;
        pa[i] = make_float4(0.f, 0.f, 0.f, 0.f);
        if (gr < M) pa[i] = *(const float4*)&A[(size_t)gr * K + aCol];
    }
    #pragma unroll
    for (int i = 0; i < 2; i++) {
        size_t off = (size_t)(bRow0 + i * 16) * N + colTile + bCol;
        pbh[i] = *(const uint4*)&Bhi[off];
        pbl[i] = *(const uint4*)&Blo[off];
    }

    #pragma unroll
    for (int i = 0; i < 4; i++) {
        int row = aRow0 + i * 32;
        __nv_bfloat162 h0, l0, h1, l1;
        split2(pa[i].x, pa[i].y, h0, l0);
        split2(pa[i].z, pa[i].w, h1, l1);
        *(__nv_bfloat162*)&As[0][0][row][aCol]     = h0;
        *(__nv_bfloat162*)&As[0][0][row][aCol + 2] = h1;
        *(__nv_bfloat162*)&As[0][1][row][aCol]     = l0;
        *(__nv_bfloat162*)&As[0][1][row][aCol + 2] = l1;
    }
    #pragma unroll
    for (int i = 0; i < 2; i++) {
        int row = bRow0 + i * 16;
        *(uint4*)&Bs[0][0][row][bCol] = pbh[i];
        *(uint4*)&Bs[0][1][row][bCol] = pbl[i];
    }
    __syncthreads();

    const int nk = K / 32;
    for (int it = 0; it < nk; it++) {
        const int buf = it & 1;
        if (it + 1 < nk) {
            const int kn = (it + 1) * 32;
            #pragma unroll
            for (int i = 0; i < 4; i++) {
                int gr = rowTile + aRow0 + i * 32;
                pa[i] = make_float4(0.f, 0.f, 0.f, 0.f);
                if (gr < M) pa[i] = *(const float4*)&A[(size_t)gr * K + kn + aCol];
            }
            #pragma unroll
            for (int i = 0; i < 2; i++) {
                size_t off = (size_t)(kn + bRow0 + i * 16) * N + colTile + bCol;
                pbh[i] = *(const uint4*)&Bhi[off];
                pbl[i] = *(const uint4*)&Blo[off];
            }
        }

        #pragma unroll
        for (int kk = 0; kk < 2; kk++) {
            const int kt = kk * 16;
            uint32_t ah[4][4], al[4][4], bh[4][2], bl[4][2];
            #pragma unroll
            for (int mt = 0; mt < 4; mt++) {
                int r = wm + mt * 16 + (lane & 15);
                int c = kt + ((lane >> 4) << 3);
                ldsm_x4(ah[mt][0], ah[mt][1], ah[mt][2], ah[mt][3], sptr(&As[buf][0][r][c]));
                ldsm_x4(al[mt][0], al[mt][1], al[mt][2], al[mt][3], sptr(&As[buf][1][r][c]));
            }
            #pragma unroll
            for (int nt = 0; nt < 4; nt++) {
                int r = kt + (lane & 15);
                int c = wn + nt * 8;
                ldsm_x2t(bh[nt][0], bh[nt][1], sptr(&Bs[buf][0][r][c]));
                ldsm_x2t(bl[nt][0], bl[nt][1], sptr(&Bs[buf][1][r][c]));
            }
            #pragma unroll
            for (int mt = 0; mt < 4; mt++)
                #pragma unroll
                for (int nt = 0; nt < 4; nt++) {
                    mma_bf16(acc[mt][nt], ah[mt], bh[nt]);
                    mma_bf16(acc[mt][nt], al[mt], bh[nt]);
                    mma_bf16(acc[mt][nt], ah[mt], bl[nt]);
                }
        }

        if (it + 1 < nk) {
            const int nb = buf ^ 1;
            #pragma unroll
            for (int i = 0; i < 4; i++) {
                int row = aRow0 + i * 32;
                __nv_bfloat162 h0, l0, h1, l1;
                split2(pa[i].x, pa[i].y, h0, l0);
                split2(pa[i].z, pa[i].w, h1, l1);
                *(__nv_bfloat162*)&As[nb][0][row][aCol]     = h0;
                *(__nv_bfloat162*)&As[nb][0][row][aCol + 2] = h1;
                *(__nv_bfloat162*)&As[nb][1][row][aCol]     = l0;
                *(__nv_bfloat162*)&As[nb][1][row][aCol + 2] = l1;
            }
            #pragma unroll
            for (int i = 0; i < 2; i++) {
                int row = bRow0 + i * 16;
                *(uint4*)&Bs[nb][0][row][bCol] = pbh[i];
                *(uint4*)&Bs[nb][1][row][bCol] = pbl[i];
            }
            __syncthreads();
        }
    }

    const int g = lane >> 2, tig = lane & 3;
    #pragma unroll
    for (int mt = 0; mt < 4; mt++) {
        #pragma unroll
        for (int nt = 0; nt < 4; nt++) {
            int row = rowTile + wm + mt * 16 + g;
            int col = colTile + wn + nt * 8 + tig * 2;
            if (row < M) {
                *(__half2*)&C[(size_t)row * N + col] =
                    __floats2half2_rn(acc[mt][nt][0], acc[mt][nt][1]);
            }
            if (row + 8 < M) {
                *(__half2*)&C[(size_t)(row + 8) * N + col] =
                    __floats2half2_rn(acc[mt][nt][2], acc[mt][nt][3]);
            }
        }
    }
}

__global__ void __launch_bounds__(256, 1)
bfgemm1_kernel(const float* __restrict__ A, int M) {
    bfgemm_body(A, &g_w1hi[0], &g_w1lo[0], &g_xw1h[0], M, D2, D1);
}
__global__ void __launch_bounds__(256, 1)
bfgemm2_kernel(int M) {
    bfgemm_body(&g_h1[0], &g_w2hi[0], &g_w2lo[0], &g_xw2h[0], M, D3, D2);
}

// ---------------- layer-1 aggregation + fused similarity projections ----------------
__global__ void aggregate1_kernel(const float* __restrict__ b1,
                                  const float* __restrict__ Wm, int n) {
    const int j = blockIdx.x;
    const int tid = threadIdx.x;  // 128
    const int lane = tid & 31, warp = tid >> 5;
    __shared__ int   s_src[128];
    __shared__ float s_w[128];
    __shared__ float red[2][4];
    const int start = g_rowptr[j];
    const int end   = g_rowptr[j + 1];
    float4 acc = make_float4(0.f, 0.f, 0.f, 0.f);
    for (int base = start; base < end; base += 128) {
        int ne = min(128, end - base);
        __syncthreads();
        if (tid < ne) { s_src[tid] = g_csr_src[base + tid]; s_w[tid] = g_csr_w[base + tid]; }
        __syncthreads();
        for (int i = 0; i < ne; i++) {
            const uint2 raw = *(const uint2*)&g_xw1h[(size_t)s_src[i] * D2 + tid * 4];
            const float2 v01 = __half22float2(*(const __half2*)&raw.x);
            const float2 v23 = __half22float2(*(const __half2*)&raw.y);
            const float w = s_w[i];
            acc.x = fmaf(w, v01.x, acc.x);
            acc.y = fmaf(w, v01.y, acc.y);
            acc.z = fmaf(w, v23.x, acc.z);
            acc.w = fmaf(w, v23.y, acc.w);
        }
    }
    const float di  = g_dinv1[j];
    const float di2 = di * di;
    const uint2 sraw = *(const uint2*)&g_xw1h[(size_t)j * D2 + tid * 4];
    const float2 s01 = __half22float2(*(const __half2*)&sraw.x);
    const float2 s23 = __half22float2(*(const __half2*)&sraw.y);
    const float4 bb = *(const float4*)&b1[tid * 4];
    float4 o;
    o.x = fmaxf(fmaf(di, acc.x, fmaf(di2, s01.x, bb.x)), 0.f);
    o.y = fmaxf(fmaf(di, acc.y, fmaf(di2, s01.y, bb.y)), 0.f);
    o.z = fmaxf(fmaf(di, acc.z, fmaf(di2, s23.x, bb.z)), 0.f);
    o.w = fmaxf(fmaf(di, acc.w, fmaf(di2, s23.y, bb.w)), 0.f);
    *(float4*)&g_h1[(size_t)j * D2 + tid * 4] = o;

    const float4 wa = *(const float4*)&Wm[tid * 4];
    const float4 wb = *(const float4*)&Wm[D2 + tid * 4];
    float sa = o.x * wa.x + o.y * wa.y + o.z * wa.z + o.w * wa.w;
    float sb = o.x * wb.x + o.y * wb.y + o.z * wb.z + o.w * wb.w;
    #pragma unroll
    for (int off = 16; off; off >>= 1) {
        sa += __shfl_down_sync(0xffffffffu, sa, off);
        sb += __shfl_down_sync(0xffffffffu, sb, off);
    }
    if (lane == 0) { red[0][warp] = sa; red[1][warp] = sb; }
    __syncthreads();
    if (tid == 0) g_ssrc[j] = red[0][0] + red[0][1] + red[0][2] + red[0][3];
    if (tid == 1) g_sdst[j] = red[1][0] + red[1][1] + red[1][2] + red[1][3];
}

// ---------------- deg2 ----------------
__global__ void deg2_kernel(const float* __restrict__ bm, int n) {
    const int j = (blockIdx.x * blockDim.x + threadIdx.x) >> 5;
    const int lane = threadIdx.x & 31;
    if (j >= n) return;
    const float sd = g_sdst[j] + bm[0];
    const int start = g_rowptr[j], end = g_rowptr[j + 1];
    float sum = 0.f;
    for (int e = start + lane; e < end; e += 32) {
        sum += fmaxf(g_ssrc[g_csr_src[e]] + sd, 0.f);
    }
    #pragma unroll
    for (int o = 16; o; o >>= 1) sum += __shfl_down_sync(0xffffffffu, sum, o);
    if (lane == 0) g_dinv2[j] = rsqrtf(1.0f + sum);
}

// ---------------- layer-2 aggregation ----------------
__global__ void aggregate2_kernel(const float* __restrict__ b2,
                                  const float* __restrict__ bm,
                                  float* __restrict__ out, int n) {
    const int j = (blockIdx.x * blockDim.x + threadIdx.x) >> 5;
    const int lane = threadIdx.x & 31;
    if (j >= n) return;
    const float sd = g_sdst[j] + bm[0];
    const int start = g_rowptr[j], end = g_rowptr[j + 1];
    float4 acc = make_float4(0.f, 0.f, 0.f, 0.f);
    for (int e = start; e < end; e++) {
        int s = g_csr_src[e];
        float w = fmaxf(g_ssrc[s] + sd, 0.f) * g_dinv2[s];
        const uint2 raw = *(const uint2*)&g_xw2h[(size_t)s * D3 + lane * 4];
        const float2 v01 = __half22float2(*(const __half2*)&raw.x);
        const float2 v23 = __half22float2(*(const __half2*)&raw.y);
        acc.x = fmaf(w, v01.x, acc.x);
        acc.y = fmaf(w, v01.y, acc.y);
        acc.z = fmaf(w, v23.x, acc.z);
        acc.w = fmaf(w, v23.y, acc.w);
    }
    const float di = g_dinv2[j];
    const float di2 = di * di;
    const uint2 sraw = *(const uint2*)&g_xw2h[(size_t)j * D3 + lane * 4];
    const float2 s01 = __half22float2(*(const __half2*)&sraw.x);
    const float2 s23 = __half22float2(*(const __half2*)&sraw.y);
    const float4 bb = *(const float4*)&b2[lane * 4];
    float4 o;
    o.x = fmaf(di, acc.x, fmaf(di2, s01.x, bb.x));
    o.y = fmaf(di, acc.y, fmaf(di2, s01.y, bb.y));
    o.z = fmaf(di, acc.z, fmaf(di2, s23.x, bb.z));
    o.w = fmaf(di, acc.w, fmaf(di2, s23.y, bb.w));
    *(float4*)&out[(size_t)j * D3 + lane * 4] = o;
}

// ---------------- launch (two-stream overlap: CSR build || GEMM1, deg2 || GEMM2) ----------------
extern "C" void kernel_launch(void* const* d_in, const int* in_sizes, int n_in,
                              void* d_out, int out_size) {
    const float* node_attr  = (const float*)d_in[0];
    const float* edge_attr  = (const float*)d_in[1];
    const int*   edge_index = (const int*)d_in[2];   // dtype auto-detected (int32/int64)
    const float* W1 = (const float*)d_in[5];
    const float* b1 = (const float*)d_in[6];
    const float* W2 = (const float*)d_in[7];
    const float* b2 = (const float*)d_in[8];
    const float* Wm = (const float*)d_in[9];
    const float* bm = (const float*)d_in[10];
    float* out = (float*)d_out;

    const int n = in_sizes[0] / D1;   // 100000
    const int E = in_sizes[1];        // 1600000

    cudaFuncSetAttribute(bfgemm1_kernel, cudaFuncAttributeMaxDynamicSharedMemorySize, SMEM_GEMM_BYTES);
    cudaFuncSetAttribute(bfgemm2_kernel, cudaFuncAttributeMaxDynamicSharedMemorySize, SMEM_GEMM_BYTES);

    // side stream + events for capture-fork (created per call; not destroyed because the
    // stream participates in graph capture; kernel_launch runs only a handful of times)
    cudaStream_t s1;
    cudaStreamCreateWithFlags(&s1, cudaStreamNonBlocking);
    cudaEvent_t evFork1, evJoin1, evFork2, evJoin2;
    cudaEventCreateWithFlags(&evFork1, cudaEventDisableTiming);
    cudaEventCreateWithFlags(&evJoin1, cudaEventDisableTiming);
    cudaEventCreateWithFlags(&evFork2, cudaEventDisableTiming);
    cudaEventCreateWithFlags(&evJoin2, cudaEventDisableTiming);

    const int TB = 256;

    // ---- fork: CSR chain on s1, weight conversion + GEMM1 on main ----
    cudaEventRecord(evFork1, 0);
    cudaStreamWaitEvent(s1, evFork1, 0);

    detect_kernel<<<1, 32, 0, s1>>>(edge_index);
    init_nodes_kernel<<<(n + TB - 1) / TB, TB, 0, s1>>>(n);
    edge_count_kernel<<<(E + TB - 1) / TB, TB, 0, s1>>>(edge_index, edge_attr, E, n);
    dinv1_kernel<<<(n + TB - 1) / TB, TB, 0, s1>>>(n);
    scan_kernel<<<1, 1024, 0, s1>>>(n);
    fill_kernel<<<(E + TB - 1) / TB, TB, 0, s1>>>(edge_index, edge_attr, E, n);
    cudaEventRecord(evJoin1, s1);

    wconv1_kernel<<<(D1 * D2 + TB - 1) / TB, TB>>>(W1);
    wconv2_kernel<<<(D2 * D3 + TB - 1) / TB, TB>>>(W2);
    {
        dim3 grid(D2 / 128, (n + 127) / 128);
        bfgemm1_kernel<<<grid, 256, SMEM_GEMM_BYTES>>>(node_attr, n);
    }

    // ---- join: aggregate1 needs both GEMM1 and CSR ----
    cudaStreamWaitEvent(0, evJoin1, 0);
    aggregate1_kernel<<<n, 128>>>(b1, Wm, n);

    // ---- fork 2: deg2 on s1 concurrent with GEMM2 ----
    cudaEventRecord(evFork2, 0);
    cudaStreamWaitEvent(s1, evFork2, 0);
    deg2_kernel<<<(n * 32 + TB - 1) / TB, TB, 0, s1>>>(bm, n);
    cudaEventRecord(evJoin2, s1);

    {
        dim3 grid(D3 / 128, (n + 127) / 128);
        bfgemm2_kernel<<<grid, 256, SMEM_GEMM_BYTES>>>(n);
    }
    cudaStreamWaitEvent(0, evJoin2, 0);
    aggregate2_kernel<<<(n * 32 + TB - 1) / TB, TB>>>(b2, bm, out, n);
}